// round 6
// baseline (speedup 1.0000x reference)
#include <cuda_runtime.h>
#include <cuda_bf16.h>
#include <cstdint>
#include <cstddef>

// Problem constants (B=8, T=4096, C=768)
#define BSZ  8
#define TLEN 4096
#define CDIM 768
#define MROWS (BSZ * TLEN)   // 32768
#define KDIM CDIM
#define ROWS3 (3 * CDIM)     // 2304 fused k|v|sr row

#define NSEG   16
#define SEGLEN (TLEN / NSEG)          // 256
#define LANES  (BSZ * CDIM)           // 6144
#define SEGTOT (LANES * NSEG)         // 98304

// ---------------- scratch (__device__ globals; no allocations allowed) -----
__device__ __align__(16) float g_kvr[MROWS * ROWS3];          // fused k|v|sr
__device__ __align__(16) __nv_bfloat16 g_ahi[MROWS * CDIM];
__device__ __align__(16) __nv_bfloat16 g_alo[MROWS * CDIM];
__device__ __align__(16) __nv_bfloat16 g_whi[4][CDIM * CDIM]; // wk,wv,wr,wo
__device__ __align__(16) __nv_bfloat16 g_wlo[4][CDIM * CDIM];
__device__ __align__(16) float g_agg [2 * SEGTOT];
__device__ __align__(16) float g_pref[2 * SEGTOT];

// ---------------- PTX helpers (sm_80-baseline only) -------------------------
__device__ __forceinline__ uint32_t smem_to_u32(const void* p) {
    uint32_t a;
    asm("{ .reg .u64 t; cvta.to.shared.u64 t, %1; cvt.u32.u64 %0, t; }"
        : "=r"(a) : "l"(p));
    return a;
}

__device__ __forceinline__ void cp_async16(uint32_t dst, const void* src) {
    asm volatile("cp.async.cg.shared.global [%0], [%1], 16;"
                 :: "r"(dst), "l"(src) : "memory");
}
#define CP_COMMIT() asm volatile("cp.async.commit_group;" ::: "memory")
template<int N>
__device__ __forceinline__ void cp_wait() {
    asm volatile("cp.async.wait_group %0;" :: "n"(N) : "memory");
}

__device__ __forceinline__ void ldsm4(uint32_t (&r)[4], uint32_t addr) {
    asm volatile("ldmatrix.sync.aligned.m8n8.x4.shared.b16 {%0,%1,%2,%3}, [%4];"
                 : "=r"(r[0]), "=r"(r[1]), "=r"(r[2]), "=r"(r[3]) : "r"(addr));
}

__device__ __forceinline__ void mma16816(float (&d)[4], const uint32_t (&a)[4],
                                         uint32_t b0, uint32_t b1) {
    asm volatile(
        "mma.sync.aligned.m16n8k16.row.col.f32.bf16.bf16.f32 "
        "{%0,%1,%2,%3}, {%4,%5,%6,%7}, {%8,%9}, {%0,%1,%2,%3};"
        : "+f"(d[0]), "+f"(d[1]), "+f"(d[2]), "+f"(d[3])
        : "r"(a[0]), "r"(a[1]), "r"(a[2]), "r"(a[3]), "r"(b0), "r"(b1));
}

// ---------------------------------------------------------------------------
// HMMA GEMM, CTA tile 128x256, warp tile 64x64 (2M x 4N warps), BK=32,
// 3-stage cp.async (1 sync/chunk), occ 1. fp32 emulated: hi*hi+hi*lo+lo*hi.
// C[m,n] = sum_k A[m,k]*B[n,k]; sigmoid applied to columns >= sigStart.
// ---------------------------------------------------------------------------
#define BKC 32
#define NCHUNK (KDIM / BKC)            // 24
#define ROW_PITCH 80
// per stage: Ahi(128) Alo(128) Bhi(256) Blo(256) rows
#define OFF_AHI 0
#define OFF_ALO (128 * ROW_PITCH)                  // 10240
#define OFF_BHI (2 * 128 * ROW_PITCH)              // 20480
#define OFF_BLO (OFF_BHI + 256 * ROW_PITCH)        // 40960
#define STAGE_BYTES (OFF_BLO + 256 * ROW_PITCH)    // 61440
#define NSTAGE 3
#define GEMM_SMEM (NSTAGE * STAGE_BYTES)           // 184320

__global__ void __launch_bounds__(256, 1) gemm_hmma_kernel(
    const __nv_bfloat16* __restrict__ Ahi, const __nv_bfloat16* __restrict__ Alo,
    const __nv_bfloat16* __restrict__ Bhi, const __nv_bfloat16* __restrict__ Blo,
    float* __restrict__ C, int ldc, int sigStart)
{
    extern __shared__ char smem[];
    const uint32_t sb = smem_to_u32(smem);
    const int tid  = threadIdx.x;
    const int wid  = tid >> 5;
    const int lane = tid & 31;
    const int rowBase = blockIdx.y * 128;
    const int colBase = blockIdx.x * 256;

    const char* srcA[2] = {
        (const char*)(Ahi + (size_t)rowBase * KDIM),
        (const char*)(Alo + (size_t)rowBase * KDIM) };
    const char* srcB[2] = {
        (const char*)(Bhi + (size_t)colBase * KDIM),
        (const char*)(Blo + (size_t)colBase * KDIM) };

    const int lr0 = tid >> 2;          // 0..63
    const int ls  = (tid & 3) * 16;    // 16B segment within 64B chunk row
    auto load_chunk = [&](int c, int stg) {
        const size_t colOff = (size_t)c * (BKC * 2);
        const uint32_t stgb = sb + (uint32_t)stg * STAGE_BYTES;
        #pragma unroll
        for (int t = 0; t < 2; t++) {
            const char* sa = srcA[t] + colOff;
            const uint32_t da = stgb + (t ? OFF_ALO : OFF_AHI);
            #pragma unroll
            for (int i = 0; i < 2; i++) {
                const int r = lr0 + i * 64;
                cp_async16(da + (uint32_t)(r * ROW_PITCH) + ls,
                           sa + (size_t)r * (KDIM * 2) + ls);
            }
            const char* sbp = srcB[t] + colOff;
            const uint32_t db = stgb + (t ? OFF_BLO : OFF_BHI);
            #pragma unroll
            for (int i = 0; i < 4; i++) {
                const int r = lr0 + i * 64;
                cp_async16(db + (uint32_t)(r * ROW_PITCH) + ls,
                           sbp + (size_t)r * (KDIM * 2) + ls);
            }
        }
    };

    const int warpM = (wid & 1) * 64;
    const int warpN = (wid >> 1) * 64;
    const uint32_t aRow  = (uint32_t)(warpM + (lane & 15));
    const uint32_t aSegL = (uint32_t)(lane >> 4);
    const uint32_t bRow  = (uint32_t)(warpN + (lane & 7) + ((lane >> 4) & 1) * 8);
    const uint32_t bSegL = (uint32_t)((lane >> 3) & 1);

    float acc[4][8][4] = {};

    auto compute = [&](int stg) {
        const uint32_t base = sb + (uint32_t)stg * STAGE_BYTES;
        #pragma unroll
        for (int ks = 0; ks < 2; ks++) {
            uint32_t bhi[4][4], blo[4][4];
            #pragma unroll
            for (int g = 0; g < 4; g++) {
                const uint32_t bd = base + OFF_BHI
                                  + (bRow + g * 16) * ROW_PITCH
                                  + (ks * 2 + bSegL) * 16;
                ldsm4(bhi[g], bd);
                ldsm4(blo[g], bd + (OFF_BLO - OFF_BHI));
            }
            #pragma unroll
            for (int mf = 0; mf < 4; mf++) {
                uint32_t ahi[4], alo[4];
                const uint32_t ad = base + OFF_AHI
                                  + (aRow + mf * 16) * ROW_PITCH
                                  + (ks * 2 + aSegL) * 16;
                ldsm4(ahi, ad);
                ldsm4(alo, ad + (OFF_ALO - OFF_AHI));
                #pragma unroll
                for (int nf = 0; nf < 8; nf++) {
                    const uint32_t b0h = bhi[nf >> 1][(nf & 1) * 2];
                    const uint32_t b1h = bhi[nf >> 1][(nf & 1) * 2 + 1];
                    const uint32_t b0l = blo[nf >> 1][(nf & 1) * 2];
                    const uint32_t b1l = blo[nf >> 1][(nf & 1) * 2 + 1];
                    mma16816(acc[mf][nf], ahi, b0h, b1h);
                    mma16816(acc[mf][nf], ahi, b0l, b1l);
                    mma16816(acc[mf][nf], alo, b0h, b1h);
                }
            }
        }
    };

    load_chunk(0, 0); CP_COMMIT();
    load_chunk(1, 1); CP_COMMIT();

    for (int c = 0; c < NCHUNK; c++) {
        cp_wait<1>();
        __syncthreads();
        if (c + 2 < NCHUNK) load_chunk(c + 2, (c + 2) % NSTAGE);
        CP_COMMIT();
        compute(c % NSTAGE);
    }

    #pragma unroll
    for (int mf = 0; mf < 4; mf++) {
        const int r0 = rowBase + warpM + mf * 16 + (lane >> 2);
        #pragma unroll
        for (int nf = 0; nf < 8; nf++) {
            const int cb = colBase + warpN + nf * 8 + (lane & 3) * 2;
            float2 lo, hi;
            lo.x = acc[mf][nf][0]; lo.y = acc[mf][nf][1];
            hi.x = acc[mf][nf][2]; hi.y = acc[mf][nf][3];
            if (cb >= sigStart) {
                lo.x = 1.0f / (1.0f + __expf(-lo.x));
                lo.y = 1.0f / (1.0f + __expf(-lo.y));
                hi.x = 1.0f / (1.0f + __expf(-hi.x));
                hi.y = 1.0f / (1.0f + __expf(-hi.y));
            }
            *(float2*)(C + (size_t)r0 * ldc + cb)       = lo;
            *(float2*)(C + (size_t)(r0 + 8) * ldc + cb) = hi;
        }
    }
}

// ---------------------------------------------------------------------------
// Elementwise: fp32 -> (hi, lo) bf16 split
// ---------------------------------------------------------------------------
__device__ __forceinline__ void split1(float v, __nv_bfloat16& h, __nv_bfloat16& l) {
    h = __float2bfloat16(v);
    l = __float2bfloat16(v - __bfloat162float(h));
}

__global__ void split_kernel(const float* __restrict__ src,
                             __nv_bfloat16* __restrict__ hi,
                             __nv_bfloat16* __restrict__ lo, int n4)
{
    int i = blockIdx.x * blockDim.x + threadIdx.x;
    if (i >= n4) return;
    float4 v = ((const float4*)src)[i];
    __nv_bfloat16 h[4], l[4];
    split1(v.x, h[0], l[0]); split1(v.y, h[1], l[1]);
    split1(v.z, h[2], l[2]); split1(v.w, h[3], l[3]);
    ((uint2*)hi)[i] = *(uint2*)h;
    ((uint2*)lo)[i] = *(uint2*)l;
}

__global__ void wsplit_kernel(const float* __restrict__ w0, const float* __restrict__ w1,
                              const float* __restrict__ w2, const float* __restrict__ w3,
                              __nv_bfloat16* __restrict__ hi,
                              __nv_bfloat16* __restrict__ lo, int n4)
{
    int i = blockIdx.x * blockDim.x + threadIdx.x;
    if (i >= n4) return;
    const float* src = (blockIdx.y == 0) ? w0 : (blockIdx.y == 1) ? w1
                     : (blockIdx.y == 2) ? w2 : w3;
    const size_t off = (size_t)blockIdx.y * (CDIM * CDIM / 4);
    float4 v = ((const float4*)src)[i];
    __nv_bfloat16 h[4], l[4];
    split1(v.x, h[0], l[0]); split1(v.y, h[1], l[1]);
    split1(v.z, h[2], l[2]); split1(v.w, h[3], l[3]);
    ((uint2*)hi)[off + i] = *(uint2*)h;
    ((uint2*)lo)[off + i] = *(uint2*)l;
}

// ---------------------------------------------------------------------------
// WKV parallel scan (unnormalized form, 1 exp/step). k|v|sr fused buffer:
// element (b,t,c): k = kvr[(b*T+t)*2304 + c], v = +768, sr = +1536.
// ---------------------------------------------------------------------------
#define WKV_U 8

__device__ __forceinline__ void wkv_load3(
    const float* __restrict__ kp, size_t base,
    float (&kb)[WKV_U], float (&vb)[WKV_U])
{
    #pragma unroll
    for (int i = 0; i < WKV_U; i++) {
        kb[i] = kp[base + (size_t)i * ROWS3];
        vb[i] = kp[base + (size_t)i * ROWS3 + CDIM];
    }
}

// Phase 1: per-(lane, seg) local aggregate from zero state
__global__ void __launch_bounds__(256) wkv_phase1(
    const float* __restrict__ kvr,
    const float* __restrict__ sd, float* __restrict__ agg)
{
    const int gid  = blockIdx.x * blockDim.x + threadIdx.x;
    const int lane = gid % LANES;
    const int seg  = gid / LANES;
    const int b = lane / CDIM, c = lane % CDIM;

    const float ew = __expf(sd[c] * (1.0f / (float)TLEN));
    const float* kp = kvr + ((size_t)b * TLEN + (size_t)seg * SEGLEN) * ROWS3 + c;

    float A = 0.0f, Bs = 0.0f;
    float k0b[WKV_U], v0b[WKV_U], k1b[WKV_U], v1b[WKV_U];
    wkv_load3(kp, 0, k0b, v0b);

    constexpr int NG = SEGLEN / WKV_U;   // 32
    for (int g = 0; g < NG; g += 2) {
        wkv_load3(kp, (size_t)(g + 1) * WKV_U * ROWS3, k1b, v1b);
        #pragma unroll
        for (int i = 0; i < WKV_U; i++) {
            const float ek = __expf(k0b[i]);
            A  = fmaf(ew, A,  ek * v0b[i]);
            Bs = fmaf(ew, Bs, ek);
        }
        if (g + 2 < NG)
            wkv_load3(kp, (size_t)(g + 2) * WKV_U * ROWS3, k0b, v0b);
        #pragma unroll
        for (int i = 0; i < WKV_U; i++) {
            const float ek = __expf(k1b[i]);
            A  = fmaf(ew, A,  ek * v1b[i]);
            Bs = fmaf(ew, Bs, ek);
        }
    }
    agg[0 * SEGTOT + gid] = A;
    agg[1 * SEGTOT + gid] = Bs;
}

// Phase 2: per-lane sequential prefix over the 16 segment aggregates
__global__ void __launch_bounds__(256) wkv_phase2(
    const float* __restrict__ agg, const float* __restrict__ sd,
    float* __restrict__ pref)
{
    const int lane = blockIdx.x * blockDim.x + threadIdx.x;
    const int c = lane % CDIM;
    const float ewseg = __expf(sd[c] * ((float)SEGLEN / (float)TLEN));

    float A = 0.0f, Bs = 0.0f;
    #pragma unroll
    for (int s = 0; s < NSEG; s++) {
        const int idx = s * LANES + lane;
        pref[0 * SEGTOT + idx] = A;
        pref[1 * SEGTOT + idx] = Bs;
        A  = fmaf(ewseg, A,  agg[0 * SEGTOT + idx]);
        Bs = fmaf(ewseg, Bs, agg[1 * SEGTOT + idx]);
    }
}

// Phase 3: replay segments; emit m = sigmoid(r)*y split to bf16 hi/lo
__global__ void __launch_bounds__(256) wkv_phase3(
    const float* __restrict__ kvr,
    const float* __restrict__ sd, const float* __restrict__ sf,
    const float* __restrict__ pref,
    __nv_bfloat16* __restrict__ mhi, __nv_bfloat16* __restrict__ mlo)
{
    const int gid  = blockIdx.x * blockDim.x + threadIdx.x;
    const int lane = gid % LANES;
    const int seg  = gid / LANES;
    const int b = lane / CDIM, c = lane % CDIM;

    const float ew = __expf(sd[c] * (1.0f / (float)TLEN));
    const float eu = __expf(sf[c] * (1.0f / (float)TLEN));
    const size_t trow = (size_t)b * TLEN + (size_t)seg * SEGLEN;
    const float* kp = kvr + trow * ROWS3 + c;
    __nv_bfloat16* hp = mhi + trow * CDIM + c;
    __nv_bfloat16* lp = mlo + trow * CDIM + c;

    float A  = pref[0 * SEGTOT + gid];
    float Bs = pref[1 * SEGTOT + gid];

    float k0b[WKV_U], v0b[WKV_U], r0b[WKV_U];
    float k1b[WKV_U], v1b[WKV_U], r1b[WKV_U];
    wkv_load3(kp, 0, k0b, v0b);
    #pragma unroll
    for (int i = 0; i < WKV_U; i++) r0b[i] = kp[(size_t)i * ROWS3 + 2 * CDIM];

    auto emit = [&](const float (&kb)[WKV_U], const float (&vb)[WKV_U],
                    const float (&rb)[WKV_U], size_t tofs) {
        #pragma unroll
        for (int i = 0; i < WKV_U; i++) {
            const float ek  = __expf(kb[i]);
            const float euk = eu * ek;
            const float y = __fdividef(fmaf(euk, vb[i], A), Bs + euk);
            const float m = y * rb[i];
            __nv_bfloat16 h, l;
            split1(m, h, l);
            hp[(tofs + i) * CDIM] = h;
            lp[(tofs + i) * CDIM] = l;
            A  = fmaf(ew, A,  ek * vb[i]);
            Bs = fmaf(ew, Bs, ek);
        }
    };

    constexpr int NG = SEGLEN / WKV_U;
    for (int g = 0; g < NG; g += 2) {
        wkv_load3(kp, (size_t)(g + 1) * WKV_U * ROWS3, k1b, v1b);
        #pragma unroll
        for (int i = 0; i < WKV_U; i++)
            r1b[i] = kp[((size_t)(g + 1) * WKV_U + i) * ROWS3 + 2 * CDIM];
        emit(k0b, v0b, r0b, (size_t)g * WKV_U);
        if (g + 2 < NG) {
            wkv_load3(kp, (size_t)(g + 2) * WKV_U * ROWS3, k0b, v0b);
            #pragma unroll
            for (int i = 0; i < WKV_U; i++)
                r0b[i] = kp[((size_t)(g + 2) * WKV_U + i) * ROWS3 + 2 * CDIM];
        }
        emit(k1b, v1b, r1b, (size_t)(g + 1) * WKV_U);
    }
}

// ---------------------------------------------------------------------------
// Launch
// ---------------------------------------------------------------------------
extern "C" void kernel_launch(void* const* d_in, const int* in_sizes, int n_in,
                              void* d_out, int out_size)
{
    const float* x  = (const float*)d_in[0];
    const float* wk = (const float*)d_in[1];
    const float* wv = (const float*)d_in[2];
    const float* wr = (const float*)d_in[3];
    const float* wo = (const float*)d_in[4];
    const float* sd = (const float*)d_in[5];
    const float* sf = (const float*)d_in[6];
    float* out = (float*)d_out;

    float *gkvr, *gagg, *gpref;
    __nv_bfloat16 *ahi, *alo, *whi, *wlo;
    cudaGetSymbolAddress((void**)&gkvr, g_kvr);
    cudaGetSymbolAddress((void**)&gagg, g_agg);
    cudaGetSymbolAddress((void**)&gpref,g_pref);
    cudaGetSymbolAddress((void**)&ahi,  g_ahi);
    cudaGetSymbolAddress((void**)&alo,  g_alo);
    cudaGetSymbolAddress((void**)&whi,  g_whi);
    cudaGetSymbolAddress((void**)&wlo,  g_wlo);

    cudaFuncSetAttribute(gemm_hmma_kernel,
                         cudaFuncAttributeMaxDynamicSharedMemorySize, GEMM_SMEM);

    const int nx4 = MROWS * CDIM / 4;
    const int nw4 = CDIM * CDIM / 4;

    split_kernel<<<(nx4 + 255) / 256, 256>>>(x, ahi, alo, nx4);
    {
        dim3 wg((nw4 + 255) / 256, 4);
        wsplit_kernel<<<wg, 256>>>(wk, wv, wr, wo, whi, wlo, nw4);
    }

    // Fused k|v|sr projection: N = 2304 (wk,wv,wr contiguous in g_whi/g_wlo),
    // sigmoid on columns >= 1536 (the sr block).
    {
        dim3 fgrid(ROWS3 / 256, MROWS / 128);   // (9, 256)
        gemm_hmma_kernel<<<fgrid, 256, GEMM_SMEM>>>(
            ahi, alo, whi, wlo, gkvr, ROWS3, 2 * CDIM);
    }

    // WKV scan + fused gate-mul + bf16 split (writes ahi/alo in place)
    wkv_phase1<<<SEGTOT / 256, 256>>>(gkvr, sd, gagg);
    wkv_phase2<<<LANES / 256, 256>>>(gagg, sd, gpref);
    wkv_phase3<<<SEGTOT / 256, 256>>>(gkvr, sd, sf, gpref, ahi, alo);

    // Output GEMM: N = 768, no sigmoid
    {
        dim3 ogrid(CDIM / 256, MROWS / 128);    // (3, 256)
        gemm_hmma_kernel<<<ogrid, 256, GEMM_SMEM>>>(
            ahi, alo, whi + 3 * (size_t)CDIM * CDIM, wlo + 3 * (size_t)CDIM * CDIM,
            out, CDIM, 1 << 30);
    }
}

// round 7
// speedup vs baseline: 1.4808x; 1.4808x over previous
#include <cuda_runtime.h>
#include <cuda_fp16.h>
#include <cstdint>
#include <cstddef>

// Problem constants (B=8, T=4096, C=768)
#define BSZ  8
#define TLEN 4096
#define CDIM 768
#define MROWS (BSZ * TLEN)   // 32768
#define KDIM CDIM
#define ROWS3 (3 * CDIM)     // 2304 fused k|v|sr row

#define NSEG   16
#define SEGLEN (TLEN / NSEG)          // 256
#define LANES  (BSZ * CDIM)           // 6144
#define SEGTOT (LANES * NSEG)         // 98304

// ---------------- scratch (__device__ globals; no allocations allowed) -----
__device__ __align__(16) float g_kvr[MROWS * ROWS3];   // fused k|v|sr
__device__ __align__(16) __half g_ahi[MROWS * CDIM];   // activation fp16 hi
__device__ __align__(16) __half g_alo[MROWS * CDIM];   // activation fp16 lo
__device__ __align__(16) __half g_w16[4][CDIM * CDIM]; // wk,wv,wr,wo fp16
__device__ __align__(16) float g_agg [2 * SEGTOT];
__device__ __align__(16) float g_pref[2 * SEGTOT];

// ---------------- PTX helpers (sm_80-baseline only) -------------------------
__device__ __forceinline__ uint32_t smem_to_u32(const void* p) {
    uint32_t a;
    asm("{ .reg .u64 t; cvta.to.shared.u64 t, %1; cvt.u32.u64 %0, t; }"
        : "=r"(a) : "l"(p));
    return a;
}

__device__ __forceinline__ void cp_async16(uint32_t dst, const void* src) {
    asm volatile("cp.async.cg.shared.global [%0], [%1], 16;"
                 :: "r"(dst), "l"(src) : "memory");
}
#define CP_COMMIT() asm volatile("cp.async.commit_group;" ::: "memory")
template<int N>
__device__ __forceinline__ void cp_wait() {
    asm volatile("cp.async.wait_group %0;" :: "n"(N) : "memory");
}

__device__ __forceinline__ void ldsm4(uint32_t (&r)[4], uint32_t addr) {
    asm volatile("ldmatrix.sync.aligned.m8n8.x4.shared.b16 {%0,%1,%2,%3}, [%4];"
                 : "=r"(r[0]), "=r"(r[1]), "=r"(r[2]), "=r"(r[3]) : "r"(addr));
}

__device__ __forceinline__ void mma16816(float (&d)[4], const uint32_t (&a)[4],
                                         uint32_t b0, uint32_t b1) {
    asm volatile(
        "mma.sync.aligned.m16n8k16.row.col.f32.f16.f16.f32 "
        "{%0,%1,%2,%3}, {%4,%5,%6,%7}, {%8,%9}, {%0,%1,%2,%3};"
        : "+f"(d[0]), "+f"(d[1]), "+f"(d[2]), "+f"(d[3])
        : "r"(a[0]), "r"(a[1]), "r"(a[2]), "r"(a[3]), "r"(b0), "r"(b1));
}

// ---------------------------------------------------------------------------
// HMMA GEMM: C[m,n] = sum_k A[m,k]*B[n,k], A = Ahi + Alo (fp16 2-term split),
// B = single fp16 plane (weights). 2 MMA products per fragment.
// CTA 128x128, warp tile 64x32 (8 warps), BK=32, 3-stage cp.async, 2 CTAs/SM.
// sigmoid applied to output columns >= sigStart.
// ---------------------------------------------------------------------------
#define BKC 32
#define NCHUNK (KDIM / BKC)            // 24
#define ROW_PITCH 80
#define TILE_BYTES (128 * ROW_PITCH)   // 10240
#define OFF_AHI 0
#define OFF_ALO TILE_BYTES
#define OFF_B   (2 * TILE_BYTES)
#define STAGE_BYTES (3 * TILE_BYTES)   // 30720
#define NSTAGE 3
#define GEMM_SMEM (NSTAGE * STAGE_BYTES)  // 92160

__global__ void __launch_bounds__(256, 2) gemm_hmma_kernel(
    const __half* __restrict__ Ahi, const __half* __restrict__ Alo,
    const __half* __restrict__ Bw,
    float* __restrict__ C, int ldc, int sigStart)
{
    extern __shared__ char smem[];
    const uint32_t sb = smem_to_u32(smem);
    const int tid  = threadIdx.x;
    const int wid  = tid >> 5;
    const int lane = tid & 31;
    const int rowBase = blockIdx.y * 128;
    const int colBase = blockIdx.x * 128;

    const char* srcs[3] = {
        (const char*)(Ahi + (size_t)rowBase * KDIM),
        (const char*)(Alo + (size_t)rowBase * KDIM),
        (const char*)(Bw  + (size_t)colBase * KDIM) };

    const int lr0 = tid >> 2;          // 0..63
    const int ls  = (tid & 3) * 16;    // 16B segment within 64B chunk row
    auto load_chunk = [&](int c, int stg) {
        const size_t colOff = (size_t)c * (BKC * 2);
        const uint32_t stgb = sb + (uint32_t)stg * STAGE_BYTES;
        #pragma unroll
        for (int t = 0; t < 3; t++) {
            const char* srcb = srcs[t] + colOff;
            const uint32_t dstb = stgb + (uint32_t)t * TILE_BYTES;
            #pragma unroll
            for (int i = 0; i < 2; i++) {
                const int r = lr0 + i * 64;
                cp_async16(dstb + (uint32_t)(r * ROW_PITCH) + ls,
                           srcb + (size_t)r * (KDIM * 2) + ls);
            }
        }
    };

    const int warpM = (wid >> 2) * 64;
    const int warpN = (wid & 3) * 32;
    const uint32_t aRow  = (uint32_t)(warpM + (lane & 15));
    const uint32_t aSegL = (uint32_t)(lane >> 4);
    const uint32_t bRow  = (uint32_t)(warpN + (lane & 7) + ((lane >> 4) & 1) * 8);
    const uint32_t bSegL = (uint32_t)((lane >> 3) & 1);

    float acc[4][4][4] = {};

    auto compute = [&](int stg) {
        const uint32_t base = sb + (uint32_t)stg * STAGE_BYTES;
        #pragma unroll
        for (int ks = 0; ks < 2; ks++) {
            uint32_t bw[2][4];
            #pragma unroll
            for (int g = 0; g < 2; g++) {
                const uint32_t bd = base + OFF_B
                                  + (bRow + g * 16) * ROW_PITCH
                                  + (ks * 2 + bSegL) * 16;
                ldsm4(bw[g], bd);
            }
            #pragma unroll
            for (int mf = 0; mf < 4; mf++) {
                uint32_t ahi[4], alo[4];
                const uint32_t ad = base + OFF_AHI
                                  + (aRow + mf * 16) * ROW_PITCH
                                  + (ks * 2 + aSegL) * 16;
                ldsm4(ahi, ad);
                ldsm4(alo, ad + (OFF_ALO - OFF_AHI));
                #pragma unroll
                for (int nf = 0; nf < 4; nf++) {
                    const uint32_t b0 = bw[nf >> 1][(nf & 1) * 2];
                    const uint32_t b1 = bw[nf >> 1][(nf & 1) * 2 + 1];
                    mma16816(acc[mf][nf], ahi, b0, b1);
                    mma16816(acc[mf][nf], alo, b0, b1);
                }
            }
        }
    };

    load_chunk(0, 0); CP_COMMIT();
    load_chunk(1, 1); CP_COMMIT();

    for (int c = 0; c < NCHUNK; c++) {
        cp_wait<1>();
        __syncthreads();
        if (c + 2 < NCHUNK) load_chunk(c + 2, (c + 2) % NSTAGE);
        CP_COMMIT();
        compute(c % NSTAGE);
    }

    #pragma unroll
    for (int mf = 0; mf < 4; mf++) {
        const int r0 = rowBase + warpM + mf * 16 + (lane >> 2);
        #pragma unroll
        for (int nf = 0; nf < 4; nf++) {
            const int cb = colBase + warpN + nf * 8 + (lane & 3) * 2;
            float2 lo, hi;
            lo.x = acc[mf][nf][0]; lo.y = acc[mf][nf][1];
            hi.x = acc[mf][nf][2]; hi.y = acc[mf][nf][3];
            if (cb >= sigStart) {
                lo.x = 1.0f / (1.0f + __expf(-lo.x));
                lo.y = 1.0f / (1.0f + __expf(-lo.y));
                hi.x = 1.0f / (1.0f + __expf(-hi.x));
                hi.y = 1.0f / (1.0f + __expf(-hi.y));
            }
            *(float2*)(C + (size_t)r0 * ldc + cb)       = lo;
            *(float2*)(C + (size_t)(r0 + 8) * ldc + cb) = hi;
        }
    }
}

// ---------------------------------------------------------------------------
// Elementwise: fp32 -> (hi, lo) fp16 split; weights -> single fp16
// ---------------------------------------------------------------------------
__device__ __forceinline__ void split1h(float v, __half& h, __half& l) {
    h = __float2half(v);
    l = __float2half(v - __half2float(h));
}

__global__ void split_kernel(const float* __restrict__ src,
                             __half* __restrict__ hi,
                             __half* __restrict__ lo, int n4)
{
    int i = blockIdx.x * blockDim.x + threadIdx.x;
    if (i >= n4) return;
    float4 v = ((const float4*)src)[i];
    __half h[4], l[4];
    split1h(v.x, h[0], l[0]); split1h(v.y, h[1], l[1]);
    split1h(v.z, h[2], l[2]); split1h(v.w, h[3], l[3]);
    ((uint2*)hi)[i] = *(uint2*)h;
    ((uint2*)lo)[i] = *(uint2*)l;
}

__global__ void wconv_kernel(const float* __restrict__ w0, const float* __restrict__ w1,
                             const float* __restrict__ w2, const float* __restrict__ w3,
                             __half* __restrict__ w16, int n4)
{
    int i = blockIdx.x * blockDim.x + threadIdx.x;
    if (i >= n4) return;
    const float* src = (blockIdx.y == 0) ? w0 : (blockIdx.y == 1) ? w1
                     : (blockIdx.y == 2) ? w2 : w3;
    const size_t off = (size_t)blockIdx.y * (CDIM * CDIM / 4);
    float4 v = ((const float4*)src)[i];
    __half h[4];
    h[0] = __float2half(v.x); h[1] = __float2half(v.y);
    h[2] = __float2half(v.z); h[3] = __float2half(v.w);
    ((uint2*)w16)[off + i] = *(uint2*)h;
}

// ---------------------------------------------------------------------------
// WKV parallel scan (unnormalized, 1 exp/step). k|v|sr fused buffer:
// (b,t,c): k = kvr[(b*T+t)*2304 + c], v = +768, sr = +1536.
// ---------------------------------------------------------------------------
#define WKV_U 8

__device__ __forceinline__ void wkv_load3(
    const float* __restrict__ kp, size_t base,
    float (&kb)[WKV_U], float (&vb)[WKV_U])
{
    #pragma unroll
    for (int i = 0; i < WKV_U; i++) {
        kb[i] = kp[base + (size_t)i * ROWS3];
        vb[i] = kp[base + (size_t)i * ROWS3 + CDIM];
    }
}

__global__ void __launch_bounds__(256) wkv_phase1(
    const float* __restrict__ kvr,
    const float* __restrict__ sd, float* __restrict__ agg)
{
    const int gid  = blockIdx.x * blockDim.x + threadIdx.x;
    const int lane = gid % LANES;
    const int seg  = gid / LANES;
    const int b = lane / CDIM, c = lane % CDIM;

    const float ew = __expf(sd[c] * (1.0f / (float)TLEN));
    const float* kp = kvr + ((size_t)b * TLEN + (size_t)seg * SEGLEN) * ROWS3 + c;

    float A = 0.0f, Bs = 0.0f;
    float k0b[WKV_U], v0b[WKV_U], k1b[WKV_U], v1b[WKV_U];
    wkv_load3(kp, 0, k0b, v0b);

    constexpr int NG = SEGLEN / WKV_U;   // 32
    for (int g = 0; g < NG; g += 2) {
        wkv_load3(kp, (size_t)(g + 1) * WKV_U * ROWS3, k1b, v1b);
        #pragma unroll
        for (int i = 0; i < WKV_U; i++) {
            const float ek = __expf(k0b[i]);
            A  = fmaf(ew, A,  ek * v0b[i]);
            Bs = fmaf(ew, Bs, ek);
        }
        if (g + 2 < NG)
            wkv_load3(kp, (size_t)(g + 2) * WKV_U * ROWS3, k0b, v0b);
        #pragma unroll
        for (int i = 0; i < WKV_U; i++) {
            const float ek = __expf(k1b[i]);
            A  = fmaf(ew, A,  ek * v1b[i]);
            Bs = fmaf(ew, Bs, ek);
        }
    }
    agg[0 * SEGTOT + gid] = A;
    agg[1 * SEGTOT + gid] = Bs;
}

__global__ void __launch_bounds__(256) wkv_phase2(
    const float* __restrict__ agg, const float* __restrict__ sd,
    float* __restrict__ pref)
{
    const int lane = blockIdx.x * blockDim.x + threadIdx.x;
    const int c = lane % CDIM;
    const float ewseg = __expf(sd[c] * ((float)SEGLEN / (float)TLEN));

    float A = 0.0f, Bs = 0.0f;
    #pragma unroll
    for (int s = 0; s < NSEG; s++) {
        const int idx = s * LANES + lane;
        pref[0 * SEGTOT + idx] = A;
        pref[1 * SEGTOT + idx] = Bs;
        A  = fmaf(ewseg, A,  agg[0 * SEGTOT + idx]);
        Bs = fmaf(ewseg, Bs, agg[1 * SEGTOT + idx]);
    }
}

// Phase 3: replay segments; emit m = sigmoid(r)*y split to fp16 hi/lo
__global__ void __launch_bounds__(256) wkv_phase3(
    const float* __restrict__ kvr,
    const float* __restrict__ sd, const float* __restrict__ sf,
    const float* __restrict__ pref,
    __half* __restrict__ mhi, __half* __restrict__ mlo)
{
    const int gid  = blockIdx.x * blockDim.x + threadIdx.x;
    const int lane = gid % LANES;
    const int seg  = gid / LANES;
    const int b = lane / CDIM, c = lane % CDIM;

    const float ew = __expf(sd[c] * (1.0f / (float)TLEN));
    const float eu = __expf(sf[c] * (1.0f / (float)TLEN));
    const size_t trow = (size_t)b * TLEN + (size_t)seg * SEGLEN;
    const float* kp = kvr + trow * ROWS3 + c;
    __half* hp = mhi + trow * CDIM + c;
    __half* lp = mlo + trow * CDIM + c;

    float A  = pref[0 * SEGTOT + gid];
    float Bs = pref[1 * SEGTOT + gid];

    float k0b[WKV_U], v0b[WKV_U], r0b[WKV_U];
    float k1b[WKV_U], v1b[WKV_U], r1b[WKV_U];
    wkv_load3(kp, 0, k0b, v0b);
    #pragma unroll
    for (int i = 0; i < WKV_U; i++) r0b[i] = kp[(size_t)i * ROWS3 + 2 * CDIM];

    auto emit = [&](const float (&kb)[WKV_U], const float (&vb)[WKV_U],
                    const float (&rb)[WKV_U], size_t tofs) {
        #pragma unroll
        for (int i = 0; i < WKV_U; i++) {
            const float ek  = __expf(kb[i]);
            const float euk = eu * ek;
            const float y = __fdividef(fmaf(euk, vb[i], A), Bs + euk);
            const float m = y * rb[i];
            __half h, l;
            split1h(m, h, l);
            hp[(tofs + i) * CDIM] = h;
            lp[(tofs + i) * CDIM] = l;
            A  = fmaf(ew, A,  ek * vb[i]);
            Bs = fmaf(ew, Bs, ek);
        }
    };

    constexpr int NG = SEGLEN / WKV_U;
    for (int g = 0; g < NG; g += 2) {
        wkv_load3(kp, (size_t)(g + 1) * WKV_U * ROWS3, k1b, v1b);
        #pragma unroll
        for (int i = 0; i < WKV_U; i++)
            r1b[i] = kp[((size_t)(g + 1) * WKV_U + i) * ROWS3 + 2 * CDIM];
        emit(k0b, v0b, r0b, (size_t)g * WKV_U);
        if (g + 2 < NG) {
            wkv_load3(kp, (size_t)(g + 2) * WKV_U * ROWS3, k0b, v0b);
            #pragma unroll
            for (int i = 0; i < WKV_U; i++)
                r0b[i] = kp[((size_t)(g + 2) * WKV_U + i) * ROWS3 + 2 * CDIM];
        }
        emit(k1b, v1b, r1b, (size_t)(g + 1) * WKV_U);
    }
}

// ---------------------------------------------------------------------------
// Launch
// ---------------------------------------------------------------------------
extern "C" void kernel_launch(void* const* d_in, const int* in_sizes, int n_in,
                              void* d_out, int out_size)
{
    const float* x  = (const float*)d_in[0];
    const float* wk = (const float*)d_in[1];
    const float* wv = (const float*)d_in[2];
    const float* wr = (const float*)d_in[3];
    const float* wo = (const float*)d_in[4];
    const float* sd = (const float*)d_in[5];
    const float* sf = (const float*)d_in[6];
    float* out = (float*)d_out;

    float *gkvr, *gagg, *gpref;
    __half *ahi, *alo, *w16;
    cudaGetSymbolAddress((void**)&gkvr, g_kvr);
    cudaGetSymbolAddress((void**)&gagg, g_agg);
    cudaGetSymbolAddress((void**)&gpref,g_pref);
    cudaGetSymbolAddress((void**)&ahi,  g_ahi);
    cudaGetSymbolAddress((void**)&alo,  g_alo);
    cudaGetSymbolAddress((void**)&w16,  g_w16);

    cudaFuncSetAttribute(gemm_hmma_kernel,
                         cudaFuncAttributeMaxDynamicSharedMemorySize, GEMM_SMEM);

    const int nx4 = MROWS * CDIM / 4;
    const int nw4 = CDIM * CDIM / 4;

    split_kernel<<<(nx4 + 255) / 256, 256>>>(x, ahi, alo, nx4);
    {
        dim3 wg((nw4 + 255) / 256, 4);
        wconv_kernel<<<wg, 256>>>(wk, wv, wr, wo, w16, nw4);
    }

    // Fused k|v|sr projection: N = 2304 (wk,wv,wr contiguous),
    // sigmoid on columns >= 1536 (the sr block).
    {
        dim3 fgrid(ROWS3 / 128, MROWS / 128);   // (18, 256)
        gemm_hmma_kernel<<<fgrid, 256, GEMM_SMEM>>>(
            ahi, alo, w16, gkvr, ROWS3, 2 * CDIM);
    }

    // WKV scan + fused gate-mul + fp16 split (writes ahi/alo in place)
    wkv_phase1<<<SEGTOT / 256, 256>>>(gkvr, sd, gagg);
    wkv_phase2<<<LANES / 256, 256>>>(gagg, sd, gpref);
    wkv_phase3<<<SEGTOT / 256, 256>>>(gkvr, sd, sf, gpref, ahi, alo);

    // Output GEMM: N = 768, no sigmoid
    {
        dim3 ogrid(CDIM / 128, MROWS / 128);    // (6, 256)
        gemm_hmma_kernel<<<ogrid, 256, GEMM_SMEM>>>(
            ahi, alo, w16 + 3 * (size_t)CDIM * CDIM, out, CDIM, 1 << 30);
    }
}

// round 8
// speedup vs baseline: 1.6273x; 1.0989x over previous
#include <cuda_runtime.h>
#include <cuda_fp16.h>
#include <cstdint>
#include <cstddef>

// Problem constants (B=8, T=4096, C=768)
#define BSZ  8
#define TLEN 4096
#define CDIM 768
#define MROWS (BSZ * TLEN)   // 32768
#define KDIM CDIM
#define ROWS3 (3 * CDIM)     // 2304 fused k|v|sr row

#define NSEG   16
#define SEGLEN (TLEN / NSEG)          // 256
#define LANES  (BSZ * CDIM)           // 6144
#define SEGTOT (LANES * NSEG)         // 98304

// ---------------- scratch (__device__ globals; no allocations allowed) -----
__device__ __align__(16) float g_kvr[MROWS * ROWS3];   // fused k|v|sr
__device__ __align__(16) __half g_ahi[MROWS * CDIM];   // activation fp16 hi
__device__ __align__(16) __half g_alo[MROWS * CDIM];   // activation fp16 lo
__device__ __align__(16) __half g_w16[4][CDIM * CDIM]; // wk,wv,wr,wo fp16
__device__ __align__(16) float g_agg [2 * SEGTOT];
__device__ __align__(16) float g_pref[2 * SEGTOT];

// ---------------- PTX helpers (sm_80-baseline only) -------------------------
__device__ __forceinline__ uint32_t smem_to_u32(const void* p) {
    uint32_t a;
    asm("{ .reg .u64 t; cvta.to.shared.u64 t, %1; cvt.u32.u64 %0, t; }"
        : "=r"(a) : "l"(p));
    return a;
}

__device__ __forceinline__ void cp_async16(uint32_t dst, const void* src) {
    asm volatile("cp.async.cg.shared.global [%0], [%1], 16;"
                 :: "r"(dst), "l"(src) : "memory");
}
#define CP_COMMIT() asm volatile("cp.async.commit_group;" ::: "memory")
template<int N>
__device__ __forceinline__ void cp_wait() {
    asm volatile("cp.async.wait_group %0;" :: "n"(N) : "memory");
}

__device__ __forceinline__ void ldsm4(uint32_t (&r)[4], uint32_t addr) {
    asm volatile("ldmatrix.sync.aligned.m8n8.x4.shared.b16 {%0,%1,%2,%3}, [%4];"
                 : "=r"(r[0]), "=r"(r[1]), "=r"(r[2]), "=r"(r[3]) : "r"(addr));
}

__device__ __forceinline__ void mma16816(float (&d)[4], const uint32_t (&a)[4],
                                         uint32_t b0, uint32_t b1) {
    asm volatile(
        "mma.sync.aligned.m16n8k16.row.col.f32.f16.f16.f32 "
        "{%0,%1,%2,%3}, {%4,%5,%6,%7}, {%8,%9}, {%0,%1,%2,%3};"
        : "+f"(d[0]), "+f"(d[1]), "+f"(d[2]), "+f"(d[3])
        : "r"(a[0]), "r"(a[1]), "r"(a[2]), "r"(a[3]), "r"(b0), "r"(b1));
}

// ---------------------------------------------------------------------------
// HMMA GEMM: C[m,n] = sum_k A[m,k]*B[n,k].
// NPROD=2: A = Ahi + Alo (fp16 split); NPROD=1: A = Ahi only.
// Dependent MMAs to the same accumulator separated by a full nf sweep.
// CTA 128x128, warp tile 64x32 (8 warps), BK=32, 3-stage cp.async, 2 CTAs/SM.
// ---------------------------------------------------------------------------
#define BKC 32
#define NCHUNK (KDIM / BKC)            // 24
#define ROW_PITCH 80
#define TILE_BYTES (128 * ROW_PITCH)   // 10240
#define OFF_AHI 0
#define OFF_ALO TILE_BYTES
#define OFF_B   (2 * TILE_BYTES)
#define STAGE_BYTES (3 * TILE_BYTES)   // 30720
#define NSTAGE 3
#define GEMM_SMEM (NSTAGE * STAGE_BYTES)  // 92160

template<int NPROD>
__global__ void __launch_bounds__(256, 2) gemm_hmma_kernel(
    const __half* __restrict__ Ahi, const __half* __restrict__ Alo,
    const __half* __restrict__ Bw,
    float* __restrict__ C, int ldc, int sigStart)
{
    extern __shared__ char smem[];
    const uint32_t sb = smem_to_u32(smem);
    const int tid  = threadIdx.x;
    const int wid  = tid >> 5;
    const int lane = tid & 31;
    const int rowBase = blockIdx.y * 128;
    const int colBase = blockIdx.x * 128;

    const char* srcs[3] = {
        (const char*)(Ahi + (size_t)rowBase * KDIM),
        (const char*)(NPROD == 2 ? (Alo + (size_t)rowBase * KDIM) : nullptr),
        (const char*)(Bw  + (size_t)colBase * KDIM) };

    const int lr0 = tid >> 2;          // 0..63
    const int ls  = (tid & 3) * 16;
    auto load_chunk = [&](int c, int stg) {
        const size_t colOff = (size_t)c * (BKC * 2);
        const uint32_t stgb = sb + (uint32_t)stg * STAGE_BYTES;
        #pragma unroll
        for (int t = 0; t < 3; t++) {
            if (NPROD == 1 && t == 1) continue;
            const char* srcb = srcs[t] + colOff;
            const uint32_t dstb = stgb + (uint32_t)t * TILE_BYTES;
            #pragma unroll
            for (int i = 0; i < 2; i++) {
                const int r = lr0 + i * 64;
                cp_async16(dstb + (uint32_t)(r * ROW_PITCH) + ls,
                           srcb + (size_t)r * (KDIM * 2) + ls);
            }
        }
    };

    const int warpM = (wid >> 2) * 64;
    const int warpN = (wid & 3) * 32;
    const uint32_t aRow  = (uint32_t)(warpM + (lane & 15));
    const uint32_t aSegL = (uint32_t)(lane >> 4);
    const uint32_t bRow  = (uint32_t)(warpN + (lane & 7) + ((lane >> 4) & 1) * 8);
    const uint32_t bSegL = (uint32_t)((lane >> 3) & 1);

    float acc[4][4][4] = {};

    auto compute = [&](int stg) {
        const uint32_t base = sb + (uint32_t)stg * STAGE_BYTES;
        #pragma unroll
        for (int ks = 0; ks < 2; ks++) {
            uint32_t bw[2][4];
            #pragma unroll
            for (int g = 0; g < 2; g++) {
                const uint32_t bd = base + OFF_B
                                  + (bRow + g * 16) * ROW_PITCH
                                  + (ks * 2 + bSegL) * 16;
                ldsm4(bw[g], bd);
            }
            #pragma unroll
            for (int mf = 0; mf < 4; mf++) {
                uint32_t ahi[4], alo[4];
                const uint32_t ad = base + OFF_AHI
                                  + (aRow + mf * 16) * ROW_PITCH
                                  + (ks * 2 + aSegL) * 16;
                ldsm4(ahi, ad);
                if (NPROD == 2) ldsm4(alo, ad + (OFF_ALO - OFF_AHI));
                // full nf sweep with ahi, THEN full sweep with alo:
                // same-acc dependent MMAs are 4 issues apart.
                #pragma unroll
                for (int nf = 0; nf < 4; nf++)
                    mma16816(acc[mf][nf], ahi,
                             bw[nf >> 1][(nf & 1) * 2], bw[nf >> 1][(nf & 1) * 2 + 1]);
                if (NPROD == 2) {
                    #pragma unroll
                    for (int nf = 0; nf < 4; nf++)
                        mma16816(acc[mf][nf], alo,
                                 bw[nf >> 1][(nf & 1) * 2], bw[nf >> 1][(nf & 1) * 2 + 1]);
                }
            }
        }
    };

    load_chunk(0, 0); CP_COMMIT();
    load_chunk(1, 1); CP_COMMIT();

    for (int c = 0; c < NCHUNK; c++) {
        cp_wait<1>();
        __syncthreads();
        if (c + 2 < NCHUNK) load_chunk(c + 2, (c + 2) % NSTAGE);
        CP_COMMIT();
        compute(c % NSTAGE);
    }

    #pragma unroll
    for (int mf = 0; mf < 4; mf++) {
        const int r0 = rowBase + warpM + mf * 16 + (lane >> 2);
        #pragma unroll
        for (int nf = 0; nf < 4; nf++) {
            const int cb = colBase + warpN + nf * 8 + (lane & 3) * 2;
            float2 lo, hi;
            lo.x = acc[mf][nf][0]; lo.y = acc[mf][nf][1];
            hi.x = acc[mf][nf][2]; hi.y = acc[mf][nf][3];
            if (cb >= sigStart) {
                lo.x = 1.0f / (1.0f + __expf(-lo.x));
                lo.y = 1.0f / (1.0f + __expf(-lo.y));
                hi.x = 1.0f / (1.0f + __expf(-hi.x));
                hi.y = 1.0f / (1.0f + __expf(-hi.y));
            }
            *(float2*)(C + (size_t)r0 * ldc + cb)       = lo;
            *(float2*)(C + (size_t)(r0 + 8) * ldc + cb) = hi;
        }
    }
}

// ---------------------------------------------------------------------------
// Elementwise: fp32 -> (hi, lo) fp16 split; weights -> single fp16
// ---------------------------------------------------------------------------
__device__ __forceinline__ void split1h(float v, __half& h, __half& l) {
    h = __float2half(v);
    l = __float2half(v - __half2float(h));
}

__global__ void split_kernel(const float* __restrict__ src,
                             __half* __restrict__ hi,
                             __half* __restrict__ lo, int n4)
{
    int i = blockIdx.x * blockDim.x + threadIdx.x;
    if (i >= n4) return;
    float4 v = ((const float4*)src)[i];
    __half h[4], l[4];
    split1h(v.x, h[0], l[0]); split1h(v.y, h[1], l[1]);
    split1h(v.z, h[2], l[2]); split1h(v.w, h[3], l[3]);
    ((uint2*)hi)[i] = *(uint2*)h;
    ((uint2*)lo)[i] = *(uint2*)l;
}

__global__ void wconv_kernel(const float* __restrict__ w0, const float* __restrict__ w1,
                             const float* __restrict__ w2, const float* __restrict__ w3,
                             __half* __restrict__ w16, int n4)
{
    int i = blockIdx.x * blockDim.x + threadIdx.x;
    if (i >= n4) return;
    const float* src = (blockIdx.y == 0) ? w0 : (blockIdx.y == 1) ? w1
                     : (blockIdx.y == 2) ? w2 : w3;
    const size_t off = (size_t)blockIdx.y * (CDIM * CDIM / 4);
    float4 v = ((const float4*)src)[i];
    __half h[4];
    h[0] = __float2half(v.x); h[1] = __float2half(v.y);
    h[2] = __float2half(v.z); h[3] = __float2half(v.w);
    ((uint2*)w16)[off + i] = *(uint2*)h;
}

// ---------------------------------------------------------------------------
// WKV parallel scan (unnormalized, 1 exp/step). k|v|sr fused buffer.
// ---------------------------------------------------------------------------
#define WKV_U 8

__device__ __forceinline__ void wkv_load3(
    const float* __restrict__ kp, size_t base,
    float (&kb)[WKV_U], float (&vb)[WKV_U])
{
    #pragma unroll
    for (int i = 0; i < WKV_U; i++) {
        kb[i] = kp[base + (size_t)i * ROWS3];
        vb[i] = kp[base + (size_t)i * ROWS3 + CDIM];
    }
}

__global__ void __launch_bounds__(256) wkv_phase1(
    const float* __restrict__ kvr,
    const float* __restrict__ sd, float* __restrict__ agg)
{
    const int gid  = blockIdx.x * blockDim.x + threadIdx.x;
    const int lane = gid % LANES;
    const int seg  = gid / LANES;
    const int b = lane / CDIM, c = lane % CDIM;

    const float ew = __expf(sd[c] * (1.0f / (float)TLEN));
    const float* kp = kvr + ((size_t)b * TLEN + (size_t)seg * SEGLEN) * ROWS3 + c;

    float A = 0.0f, Bs = 0.0f;
    float k0b[WKV_U], v0b[WKV_U], k1b[WKV_U], v1b[WKV_U];
    wkv_load3(kp, 0, k0b, v0b);

    constexpr int NG = SEGLEN / WKV_U;   // 32
    for (int g = 0; g < NG; g += 2) {
        wkv_load3(kp, (size_t)(g + 1) * WKV_U * ROWS3, k1b, v1b);
        #pragma unroll
        for (int i = 0; i < WKV_U; i++) {
            const float ek = __expf(k0b[i]);
            A  = fmaf(ew, A,  ek * v0b[i]);
            Bs = fmaf(ew, Bs, ek);
        }
        if (g + 2 < NG)
            wkv_load3(kp, (size_t)(g + 2) * WKV_U * ROWS3, k0b, v0b);
        #pragma unroll
        for (int i = 0; i < WKV_U; i++) {
            const float ek = __expf(k1b[i]);
            A  = fmaf(ew, A,  ek * v1b[i]);
            Bs = fmaf(ew, Bs, ek);
        }
    }
    agg[0 * SEGTOT + gid] = A;
    agg[1 * SEGTOT + gid] = Bs;
}

__global__ void __launch_bounds__(256) wkv_phase2(
    const float* __restrict__ agg, const float* __restrict__ sd,
    float* __restrict__ pref)
{
    const int lane = blockIdx.x * blockDim.x + threadIdx.x;
    const int c = lane % CDIM;
    const float ewseg = __expf(sd[c] * ((float)SEGLEN / (float)TLEN));

    float A = 0.0f, Bs = 0.0f;
    #pragma unroll
    for (int s = 0; s < NSEG; s++) {
        const int idx = s * LANES + lane;
        pref[0 * SEGTOT + idx] = A;
        pref[1 * SEGTOT + idx] = Bs;
        A  = fmaf(ewseg, A,  agg[0 * SEGTOT + idx]);
        Bs = fmaf(ewseg, Bs, agg[1 * SEGTOT + idx]);
    }
}

// Phase 3: replay segments; emit m = sigmoid(r)*y directly as fp16 (single plane)
__global__ void __launch_bounds__(256) wkv_phase3(
    const float* __restrict__ kvr,
    const float* __restrict__ sd, const float* __restrict__ sf,
    const float* __restrict__ pref,
    __half* __restrict__ mhi)
{
    const int gid  = blockIdx.x * blockDim.x + threadIdx.x;
    const int lane = gid % LANES;
    const int seg  = gid / LANES;
    const int b = lane / CDIM, c = lane % CDIM;

    const float ew = __expf(sd[c] * (1.0f / (float)TLEN));
    const float eu = __expf(sf[c] * (1.0f / (float)TLEN));
    const size_t trow = (size_t)b * TLEN + (size_t)seg * SEGLEN;
    const float* kp = kvr + trow * ROWS3 + c;
    __half* hp = mhi + trow * CDIM + c;

    float A  = pref[0 * SEGTOT + gid];
    float Bs = pref[1 * SEGTOT + gid];

    float k0b[WKV_U], v0b[WKV_U], r0b[WKV_U];
    float k1b[WKV_U], v1b[WKV_U], r1b[WKV_U];
    wkv_load3(kp, 0, k0b, v0b);
    #pragma unroll
    for (int i = 0; i < WKV_U; i++) r0b[i] = kp[(size_t)i * ROWS3 + 2 * CDIM];

    auto emit = [&](const float (&kb)[WKV_U], const float (&vb)[WKV_U],
                    const float (&rb)[WKV_U], size_t tofs) {
        #pragma unroll
        for (int i = 0; i < WKV_U; i++) {
            const float ek  = __expf(kb[i]);
            const float euk = eu * ek;
            const float y = __fdividef(fmaf(euk, vb[i], A), Bs + euk);
            hp[(tofs + i) * CDIM] = __float2half(y * rb[i]);
            A  = fmaf(ew, A,  ek * vb[i]);
            Bs = fmaf(ew, Bs, ek);
        }
    };

    constexpr int NG = SEGLEN / WKV_U;
    for (int g = 0; g < NG; g += 2) {
        wkv_load3(kp, (size_t)(g + 1) * WKV_U * ROWS3, k1b, v1b);
        #pragma unroll
        for (int i = 0; i < WKV_U; i++)
            r1b[i] = kp[((size_t)(g + 1) * WKV_U + i) * ROWS3 + 2 * CDIM];
        emit(k0b, v0b, r0b, (size_t)g * WKV_U);
        if (g + 2 < NG) {
            wkv_load3(kp, (size_t)(g + 2) * WKV_U * ROWS3, k0b, v0b);
            #pragma unroll
            for (int i = 0; i < WKV_U; i++)
                r0b[i] = kp[((size_t)(g + 2) * WKV_U + i) * ROWS3 + 2 * CDIM];
        }
        emit(k1b, v1b, r1b, (size_t)(g + 1) * WKV_U);
    }
}

// ---------------------------------------------------------------------------
// Launch
// ---------------------------------------------------------------------------
extern "C" void kernel_launch(void* const* d_in, const int* in_sizes, int n_in,
                              void* d_out, int out_size)
{
    const float* x  = (const float*)d_in[0];
    const float* wk = (const float*)d_in[1];
    const float* wv = (const float*)d_in[2];
    const float* wr = (const float*)d_in[3];
    const float* wo = (const float*)d_in[4];
    const float* sd = (const float*)d_in[5];
    const float* sf = (const float*)d_in[6];
    float* out = (float*)d_out;

    float *gkvr, *gagg, *gpref;
    __half *ahi, *alo, *w16;
    cudaGetSymbolAddress((void**)&gkvr, g_kvr);
    cudaGetSymbolAddress((void**)&gagg, g_agg);
    cudaGetSymbolAddress((void**)&gpref,g_pref);
    cudaGetSymbolAddress((void**)&ahi,  g_ahi);
    cudaGetSymbolAddress((void**)&alo,  g_alo);
    cudaGetSymbolAddress((void**)&w16,  g_w16);

    cudaFuncSetAttribute(gemm_hmma_kernel<2>,
                         cudaFuncAttributeMaxDynamicSharedMemorySize, GEMM_SMEM);
    cudaFuncSetAttribute(gemm_hmma_kernel<1>,
                         cudaFuncAttributeMaxDynamicSharedMemorySize, GEMM_SMEM);

    const int nx4 = MROWS * CDIM / 4;
    const int nw4 = CDIM * CDIM / 4;

    split_kernel<<<(nx4 + 255) / 256, 256>>>(x, ahi, alo, nx4);
    {
        dim3 wg((nw4 + 255) / 256, 4);
        wconv_kernel<<<wg, 256>>>(wk, wv, wr, wo, w16, nw4);
    }

    // Fused k|v|sr projection (2-term split A), sigmoid on cols >= 1536
    {
        dim3 fgrid(ROWS3 / 128, MROWS / 128);   // (18, 256)
        gemm_hmma_kernel<2><<<fgrid, 256, GEMM_SMEM>>>(
            ahi, alo, w16, gkvr, ROWS3, 2 * CDIM);
    }

    // WKV scan + fused gate-mul; emits single-plane fp16 m into ahi
    wkv_phase1<<<SEGTOT / 256, 256>>>(gkvr, sd, gagg);
    wkv_phase2<<<LANES / 256, 256>>>(gagg, sd, gpref);
    wkv_phase3<<<SEGTOT / 256, 256>>>(gkvr, sd, sf, gpref, ahi);

    // Output GEMM: single-product (m is plain fp16), N = 768
    {
        dim3 ogrid(CDIM / 128, MROWS / 128);    // (6, 256)
        gemm_hmma_kernel<1><<<ogrid, 256, GEMM_SMEM>>>(
            ahi, nullptr, w16 + 3 * (size_t)CDIM * CDIM, out, CDIM, 1 << 30);
    }
}

// round 9
// speedup vs baseline: 2.3483x; 1.4431x over previous
#include <cuda_runtime.h>
#include <cuda_fp16.h>
#include <cstdint>
#include <cstddef>

// Problem constants (B=8, T=4096, C=768)
#define BSZ  8
#define TLEN 4096
#define CDIM 768
#define MROWS (BSZ * TLEN)   // 32768
#define KDIM CDIM
#define ROWS3 (3 * CDIM)     // 2304 fused k|v|sr row

#define NSEG   16
#define SEGLEN (TLEN / NSEG)          // 256
#define LANES  (BSZ * CDIM)           // 6144
#define SEGTOT (LANES * NSEG)         // 98304

// ---------------- scratch (__device__ globals; no allocations allowed) -----
__device__ __align__(16) float g_kvr[MROWS * ROWS3];   // fused k|v|sr
__device__ __align__(16) __half g_a16[MROWS * CDIM];   // activation fp16 (x, then m)
__device__ __align__(16) __half g_w16[4][CDIM * CDIM]; // wk,wv,wr,wo fp16
__device__ __align__(16) float g_agg [2 * SEGTOT];
__device__ __align__(16) float g_pref[2 * SEGTOT];

// ---------------- PTX helpers (sm_80-baseline only) -------------------------
__device__ __forceinline__ uint32_t smem_to_u32(const void* p) {
    uint32_t a;
    asm("{ .reg .u64 t; cvta.to.shared.u64 t, %1; cvt.u32.u64 %0, t; }"
        : "=r"(a) : "l"(p));
    return a;
}

__device__ __forceinline__ void cp_async16(uint32_t dst, const void* src) {
    asm volatile("cp.async.cg.shared.global [%0], [%1], 16;"
                 :: "r"(dst), "l"(src) : "memory");
}
#define CP_COMMIT() asm volatile("cp.async.commit_group;" ::: "memory")
template<int N>
__device__ __forceinline__ void cp_wait() {
    asm volatile("cp.async.wait_group %0;" :: "n"(N) : "memory");
}

__device__ __forceinline__ void ldsm4(uint32_t (&r)[4], uint32_t addr) {
    asm volatile("ldmatrix.sync.aligned.m8n8.x4.shared.b16 {%0,%1,%2,%3}, [%4];"
                 : "=r"(r[0]), "=r"(r[1]), "=r"(r[2]), "=r"(r[3]) : "r"(addr));
}

__device__ __forceinline__ void mma16816(float (&d)[4], const uint32_t (&a)[4],
                                         uint32_t b0, uint32_t b1) {
    asm volatile(
        "mma.sync.aligned.m16n8k16.row.col.f32.f16.f16.f32 "
        "{%0,%1,%2,%3}, {%4,%5,%6,%7}, {%8,%9}, {%0,%1,%2,%3};"
        : "+f"(d[0]), "+f"(d[1]), "+f"(d[2]), "+f"(d[3])
        : "r"(a[0]), "r"(a[1]), "r"(a[2]), "r"(a[3]), "r"(b0), "r"(b1));
}

// ---------------------------------------------------------------------------
// HMMA GEMM: C[m,n] = sum_k A[m,k]*B[n,k], single fp16 product.
// CTA 128x128, warp tile 64x32 (8 warps), BK=32, 3-stage cp.async, 2 CTAs/SM.
// sigmoid applied to output columns >= sigStart.
// ---------------------------------------------------------------------------
#define BKC 32
#define NCHUNK (KDIM / BKC)            // 24
#define ROW_PITCH 80
#define TILE_BYTES (128 * ROW_PITCH)   // 10240
#define OFF_A 0
#define OFF_B TILE_BYTES
#define STAGE_BYTES (2 * TILE_BYTES)   // 20480
#define NSTAGE 3
#define GEMM_SMEM (NSTAGE * STAGE_BYTES)  // 61440

__global__ void __launch_bounds__(256, 2) gemm_hmma_kernel(
    const __half* __restrict__ Aa, const __half* __restrict__ Bw,
    float* __restrict__ C, int ldc, int sigStart)
{
    extern __shared__ char smem[];
    const uint32_t sb = smem_to_u32(smem);
    const int tid  = threadIdx.x;
    const int wid  = tid >> 5;
    const int lane = tid & 31;
    const int rowBase = blockIdx.y * 128;
    const int colBase = blockIdx.x * 128;

    const char* srcs[2] = {
        (const char*)(Aa + (size_t)rowBase * KDIM),
        (const char*)(Bw + (size_t)colBase * KDIM) };

    const int lr0 = tid >> 2;          // 0..63
    const int ls  = (tid & 3) * 16;
    auto load_chunk = [&](int c, int stg) {
        const size_t colOff = (size_t)c * (BKC * 2);
        const uint32_t stgb = sb + (uint32_t)stg * STAGE_BYTES;
        #pragma unroll
        for (int t = 0; t < 2; t++) {
            const char* srcb = srcs[t] + colOff;
            const uint32_t dstb = stgb + (uint32_t)t * TILE_BYTES;
            #pragma unroll
            for (int i = 0; i < 2; i++) {
                const int r = lr0 + i * 64;
                cp_async16(dstb + (uint32_t)(r * ROW_PITCH) + ls,
                           srcb + (size_t)r * (KDIM * 2) + ls);
            }
        }
    };

    const int warpM = (wid >> 2) * 64;
    const int warpN = (wid & 3) * 32;
    const uint32_t aRow  = (uint32_t)(warpM + (lane & 15));
    const uint32_t aSegL = (uint32_t)(lane >> 4);
    const uint32_t bRow  = (uint32_t)(warpN + (lane & 7) + ((lane >> 4) & 1) * 8);
    const uint32_t bSegL = (uint32_t)((lane >> 3) & 1);

    float acc[4][4][4] = {};

    auto compute = [&](int stg) {
        const uint32_t base = sb + (uint32_t)stg * STAGE_BYTES;
        #pragma unroll
        for (int ks = 0; ks < 2; ks++) {
            uint32_t bw[2][4];
            #pragma unroll
            for (int g = 0; g < 2; g++) {
                const uint32_t bd = base + OFF_B
                                  + (bRow + g * 16) * ROW_PITCH
                                  + (ks * 2 + bSegL) * 16;
                ldsm4(bw[g], bd);
            }
            #pragma unroll
            for (int mf = 0; mf < 4; mf++) {
                uint32_t af[4];
                const uint32_t ad = base + OFF_A
                                  + (aRow + mf * 16) * ROW_PITCH
                                  + (ks * 2 + aSegL) * 16;
                ldsm4(af, ad);
                #pragma unroll
                for (int nf = 0; nf < 4; nf++)
                    mma16816(acc[mf][nf], af,
                             bw[nf >> 1][(nf & 1) * 2], bw[nf >> 1][(nf & 1) * 2 + 1]);
            }
        }
    };

    load_chunk(0, 0); CP_COMMIT();
    load_chunk(1, 1); CP_COMMIT();

    for (int c = 0; c < NCHUNK; c++) {
        cp_wait<1>();
        __syncthreads();
        if (c + 2 < NCHUNK) load_chunk(c + 2, (c + 2) % NSTAGE);
        CP_COMMIT();
        compute(c % NSTAGE);
    }

    #pragma unroll
    for (int mf = 0; mf < 4; mf++) {
        const int r0 = rowBase + warpM + mf * 16 + (lane >> 2);
        #pragma unroll
        for (int nf = 0; nf < 4; nf++) {
            const int cb = colBase + warpN + nf * 8 + (lane & 3) * 2;
            float2 lo, hi;
            lo.x = acc[mf][nf][0]; lo.y = acc[mf][nf][1];
            hi.x = acc[mf][nf][2]; hi.y = acc[mf][nf][3];
            if (cb >= sigStart) {
                lo.x = 1.0f / (1.0f + __expf(-lo.x));
                lo.y = 1.0f / (1.0f + __expf(-lo.y));
                hi.x = 1.0f / (1.0f + __expf(-hi.x));
                hi.y = 1.0f / (1.0f + __expf(-hi.y));
            }
            *(float2*)(C + (size_t)r0 * ldc + cb)       = lo;
            *(float2*)(C + (size_t)(r0 + 8) * ldc + cb) = hi;
        }
    }
}

// ---------------------------------------------------------------------------
// Elementwise converts: fp32 -> fp16
// ---------------------------------------------------------------------------
__global__ void xconv_kernel(const float* __restrict__ src,
                             __half* __restrict__ dst, int n4)
{
    int i = blockIdx.x * blockDim.x + threadIdx.x;
    if (i >= n4) return;
    float4 v = ((const float4*)src)[i];
    __half h[4];
    h[0] = __float2half(v.x); h[1] = __float2half(v.y);
    h[2] = __float2half(v.z); h[3] = __float2half(v.w);
    ((uint2*)dst)[i] = *(uint2*)h;
}

__global__ void wconv_kernel(const float* __restrict__ w0, const float* __restrict__ w1,
                             const float* __restrict__ w2, const float* __restrict__ w3,
                             __half* __restrict__ w16, int n4)
{
    int i = blockIdx.x * blockDim.x + threadIdx.x;
    if (i >= n4) return;
    const float* src = (blockIdx.y == 0) ? w0 : (blockIdx.y == 1) ? w1
                     : (blockIdx.y == 2) ? w2 : w3;
    const size_t off = (size_t)blockIdx.y * (CDIM * CDIM / 4);
    float4 v = ((const float4*)src)[i];
    __half h[4];
    h[0] = __float2half(v.x); h[1] = __float2half(v.y);
    h[2] = __float2half(v.z); h[3] = __float2half(v.w);
    ((uint2*)w16)[off + i] = *(uint2*)h;
}

// ---------------------------------------------------------------------------
// WKV parallel scan (unnormalized, 1 exp/step). k|v|sr fused buffer:
// (b,t,c): k = kvr[(b*T+t)*2304 + c], v = +768, sr = +1536.
// ---------------------------------------------------------------------------
#define WKV_U 8

__device__ __forceinline__ void wkv_load3(
    const float* __restrict__ kp, size_t base,
    float (&kb)[WKV_U], float (&vb)[WKV_U])
{
    #pragma unroll
    for (int i = 0; i < WKV_U; i++) {
        kb[i] = kp[base + (size_t)i * ROWS3];
        vb[i] = kp[base + (size_t)i * ROWS3 + CDIM];
    }
}

__global__ void __launch_bounds__(256) wkv_phase1(
    const float* __restrict__ kvr,
    const float* __restrict__ sd, float* __restrict__ agg)
{
    const int gid  = blockIdx.x * blockDim.x + threadIdx.x;
    const int lane = gid % LANES;
    const int seg  = gid / LANES;
    const int b = lane / CDIM, c = lane % CDIM;

    const float ew = __expf(sd[c] * (1.0f / (float)TLEN));
    const float* kp = kvr + ((size_t)b * TLEN + (size_t)seg * SEGLEN) * ROWS3 + c;

    float A = 0.0f, Bs = 0.0f;
    float k0b[WKV_U], v0b[WKV_U], k1b[WKV_U], v1b[WKV_U];
    wkv_load3(kp, 0, k0b, v0b);

    constexpr int NG = SEGLEN / WKV_U;   // 32
    for (int g = 0; g < NG; g += 2) {
        wkv_load3(kp, (size_t)(g + 1) * WKV_U * ROWS3, k1b, v1b);
        #pragma unroll
        for (int i = 0; i < WKV_U; i++) {
            const float ek = __expf(k0b[i]);
            A  = fmaf(ew, A,  ek * v0b[i]);
            Bs = fmaf(ew, Bs, ek);
        }
        if (g + 2 < NG)
            wkv_load3(kp, (size_t)(g + 2) * WKV_U * ROWS3, k0b, v0b);
        #pragma unroll
        for (int i = 0; i < WKV_U; i++) {
            const float ek = __expf(k1b[i]);
            A  = fmaf(ew, A,  ek * v1b[i]);
            Bs = fmaf(ew, Bs, ek);
        }
    }
    agg[0 * SEGTOT + gid] = A;
    agg[1 * SEGTOT + gid] = Bs;
}

__global__ void __launch_bounds__(256) wkv_phase2(
    const float* __restrict__ agg, const float* __restrict__ sd,
    float* __restrict__ pref)
{
    const int lane = blockIdx.x * blockDim.x + threadIdx.x;
    const int c = lane % CDIM;
    const float ewseg = __expf(sd[c] * ((float)SEGLEN / (float)TLEN));

    float A = 0.0f, Bs = 0.0f;
    #pragma unroll
    for (int s = 0; s < NSEG; s++) {
        const int idx = s * LANES + lane;
        pref[0 * SEGTOT + idx] = A;
        pref[1 * SEGTOT + idx] = Bs;
        A  = fmaf(ewseg, A,  agg[0 * SEGTOT + idx]);
        Bs = fmaf(ewseg, Bs, agg[1 * SEGTOT + idx]);
    }
}

// Phase 3: replay segments; emit m = sigmoid(r)*y directly as fp16
__global__ void __launch_bounds__(256) wkv_phase3(
    const float* __restrict__ kvr,
    const float* __restrict__ sd, const float* __restrict__ sf,
    const float* __restrict__ pref,
    __half* __restrict__ mh)
{
    const int gid  = blockIdx.x * blockDim.x + threadIdx.x;
    const int lane = gid % LANES;
    const int seg  = gid / LANES;
    const int b = lane / CDIM, c = lane % CDIM;

    const float ew = __expf(sd[c] * (1.0f / (float)TLEN));
    const float eu = __expf(sf[c] * (1.0f / (float)TLEN));
    const size_t trow = (size_t)b * TLEN + (size_t)seg * SEGLEN;
    const float* kp = kvr + trow * ROWS3 + c;
    __half* hp = mh + trow * CDIM + c;

    float A  = pref[0 * SEGTOT + gid];
    float Bs = pref[1 * SEGTOT + gid];

    float k0b[WKV_U], v0b[WKV_U], r0b[WKV_U];
    float k1b[WKV_U], v1b[WKV_U], r1b[WKV_U];
    wkv_load3(kp, 0, k0b, v0b);
    #pragma unroll
    for (int i = 0; i < WKV_U; i++) r0b[i] = kp[(size_t)i * ROWS3 + 2 * CDIM];

    auto emit = [&](const float (&kb)[WKV_U], const float (&vb)[WKV_U],
                    const float (&rb)[WKV_U], size_t tofs) {
        #pragma unroll
        for (int i = 0; i < WKV_U; i++) {
            const float ek  = __expf(kb[i]);
            const float euk = eu * ek;
            const float y = __fdividef(fmaf(euk, vb[i], A), Bs + euk);
            hp[(tofs + i) * CDIM] = __float2half(y * rb[i]);
            A  = fmaf(ew, A,  ek * vb[i]);
            Bs = fmaf(ew, Bs, ek);
        }
    };

    constexpr int NG = SEGLEN / WKV_U;
    for (int g = 0; g < NG; g += 2) {
        wkv_load3(kp, (size_t)(g + 1) * WKV_U * ROWS3, k1b, v1b);
        #pragma unroll
        for (int i = 0; i < WKV_U; i++)
            r1b[i] = kp[((size_t)(g + 1) * WKV_U + i) * ROWS3 + 2 * CDIM];
        emit(k0b, v0b, r0b, (size_t)g * WKV_U);
        if (g + 2 < NG) {
            wkv_load3(kp, (size_t)(g + 2) * WKV_U * ROWS3, k0b, v0b);
            #pragma unroll
            for (int i = 0; i < WKV_U; i++)
                r0b[i] = kp[((size_t)(g + 2) * WKV_U + i) * ROWS3 + 2 * CDIM];
        }
        emit(k1b, v1b, r1b, (size_t)(g + 1) * WKV_U);
    }
}

// ---------------------------------------------------------------------------
// Launch
// ---------------------------------------------------------------------------
extern "C" void kernel_launch(void* const* d_in, const int* in_sizes, int n_in,
                              void* d_out, int out_size)
{
    const float* x  = (const float*)d_in[0];
    const float* wk = (const float*)d_in[1];
    const float* wv = (const float*)d_in[2];
    const float* wr = (const float*)d_in[3];
    const float* wo = (const float*)d_in[4];
    const float* sd = (const float*)d_in[5];
    const float* sf = (const float*)d_in[6];
    float* out = (float*)d_out;

    float *gkvr, *gagg, *gpref;
    __half *a16, *w16;
    cudaGetSymbolAddress((void**)&gkvr, g_kvr);
    cudaGetSymbolAddress((void**)&gagg, g_agg);
    cudaGetSymbolAddress((void**)&gpref,g_pref);
    cudaGetSymbolAddress((void**)&a16,  g_a16);
    cudaGetSymbolAddress((void**)&w16,  g_w16);

    cudaFuncSetAttribute(gemm_hmma_kernel,
                         cudaFuncAttributeMaxDynamicSharedMemorySize, GEMM_SMEM);

    const int nx4 = MROWS * CDIM / 4;
    const int nw4 = CDIM * CDIM / 4;

    xconv_kernel<<<(nx4 + 255) / 256, 256>>>(x, a16, nx4);
    {
        dim3 wg((nw4 + 255) / 256, 4);
        wconv_kernel<<<wg, 256>>>(wk, wv, wr, wo, w16, nw4);
    }

    // Fused k|v|sr projection (single product), sigmoid on cols >= 1536
    {
        dim3 fgrid(ROWS3 / 128, MROWS / 128);   // (18, 256)
        gemm_hmma_kernel<<<fgrid, 256, GEMM_SMEM>>>(
            a16, w16, gkvr, ROWS3, 2 * CDIM);
    }

    // WKV scan + fused gate-mul; emits fp16 m into a16
    wkv_phase1<<<SEGTOT / 256, 256>>>(gkvr, sd, gagg);
    wkv_phase2<<<LANES / 256, 256>>>(gagg, sd, gpref);
    wkv_phase3<<<SEGTOT / 256, 256>>>(gkvr, sd, sf, gpref, a16);

    // Output GEMM: single product, N = 768
    {
        dim3 ogrid(CDIM / 128, MROWS / 128);    // (6, 256)
        gemm_hmma_kernel<<<ogrid, 256, GEMM_SMEM>>>(
            a16, w16 + 3 * (size_t)CDIM * CDIM, out, CDIM, 1 << 30);
    }
}

// round 10
// speedup vs baseline: 2.4003x; 1.0221x over previous
#include <cuda_runtime.h>
#include <cuda_fp16.h>
#include <cstdint>
#include <cstddef>

// Problem constants (B=8, T=4096, C=768)
#define BSZ  8
#define TLEN 4096
#define CDIM 768
#define MROWS (BSZ * TLEN)   // 32768
#define KDIM CDIM
#define ROWS3 (3 * CDIM)     // 2304 fused k|v|sr row

#define NSEG   16
#define SEGLEN (TLEN / NSEG)          // 256
#define LANES  (BSZ * CDIM)           // 6144
#define SEGTOT (LANES * NSEG)         // 98304

// ---------------- scratch (__device__ globals; no allocations allowed) -----
__device__ __align__(16) __half g_kvr[MROWS * ROWS3]; // fused k|v|sr, fp16
__device__ __align__(16) __half g_a16[MROWS * CDIM];  // activation fp16 (x, then m)
__device__ __align__(16) __half g_w16[4][CDIM * CDIM];// wk,wv,wr,wo fp16
__device__ __align__(16) float g_agg [2 * SEGTOT];
__device__ __align__(16) float g_pref[2 * SEGTOT];

// ---------------- PTX helpers (sm_80-baseline only) -------------------------
__device__ __forceinline__ uint32_t smem_to_u32(const void* p) {
    uint32_t a;
    asm("{ .reg .u64 t; cvta.to.shared.u64 t, %1; cvt.u32.u64 %0, t; }"
        : "=r"(a) : "l"(p));
    return a;
}

__device__ __forceinline__ void cp_async16(uint32_t dst, const void* src) {
    asm volatile("cp.async.cg.shared.global [%0], [%1], 16;"
                 :: "r"(dst), "l"(src) : "memory");
}
#define CP_COMMIT() asm volatile("cp.async.commit_group;" ::: "memory")
template<int N>
__device__ __forceinline__ void cp_wait() {
    asm volatile("cp.async.wait_group %0;" :: "n"(N) : "memory");
}

__device__ __forceinline__ void ldsm4(uint32_t (&r)[4], uint32_t addr) {
    asm volatile("ldmatrix.sync.aligned.m8n8.x4.shared.b16 {%0,%1,%2,%3}, [%4];"
                 : "=r"(r[0]), "=r"(r[1]), "=r"(r[2]), "=r"(r[3]) : "r"(addr));
}

__device__ __forceinline__ void mma16816(float (&d)[4], const uint32_t (&a)[4],
                                         uint32_t b0, uint32_t b1) {
    asm volatile(
        "mma.sync.aligned.m16n8k16.row.col.f32.f16.f16.f32 "
        "{%0,%1,%2,%3}, {%4,%5,%6,%7}, {%8,%9}, {%0,%1,%2,%3};"
        : "+f"(d[0]), "+f"(d[1]), "+f"(d[2]), "+f"(d[3])
        : "r"(a[0]), "r"(a[1]), "r"(a[2]), "r"(a[3]), "r"(b0), "r"(b1));
}

// ---------------------------------------------------------------------------
// HMMA GEMM: C[m,n] = sum_k A[m,k]*B[n,k], single fp16 product.
// CTA 128x128, warp tile 64x32 (8 warps), BK=32, 3-stage cp.async, 2 CTAs/SM.
// OutT = __half (fp16 store, sigmoid on cols >= sigStart) or float.
// ---------------------------------------------------------------------------
#define BKC 32
#define NCHUNK (KDIM / BKC)            // 24
#define ROW_PITCH 80
#define TILE_BYTES (128 * ROW_PITCH)   // 10240
#define OFF_A 0
#define OFF_B TILE_BYTES
#define STAGE_BYTES (2 * TILE_BYTES)   // 20480
#define NSTAGE 3
#define GEMM_SMEM (NSTAGE * STAGE_BYTES)  // 61440

template<typename OutT>
__global__ void __launch_bounds__(256, 2) gemm_hmma_kernel(
    const __half* __restrict__ Aa, const __half* __restrict__ Bw,
    OutT* __restrict__ C, int ldc, int sigStart)
{
    extern __shared__ char smem[];
    const uint32_t sb = smem_to_u32(smem);
    const int tid  = threadIdx.x;
    const int wid  = tid >> 5;
    const int lane = tid & 31;
    const int rowBase = blockIdx.y * 128;
    const int colBase = blockIdx.x * 128;

    const char* srcs[2] = {
        (const char*)(Aa + (size_t)rowBase * KDIM),
        (const char*)(Bw + (size_t)colBase * KDIM) };

    const int lr0 = tid >> 2;          // 0..63
    const int ls  = (tid & 3) * 16;
    auto load_chunk = [&](int c, int stg) {
        const size_t colOff = (size_t)c * (BKC * 2);
        const uint32_t stgb = sb + (uint32_t)stg * STAGE_BYTES;
        #pragma unroll
        for (int t = 0; t < 2; t++) {
            const char* srcb = srcs[t] + colOff;
            const uint32_t dstb = stgb + (uint32_t)t * TILE_BYTES;
            #pragma unroll
            for (int i = 0; i < 2; i++) {
                const int r = lr0 + i * 64;
                cp_async16(dstb + (uint32_t)(r * ROW_PITCH) + ls,
                           srcb + (size_t)r * (KDIM * 2) + ls);
            }
        }
    };

    const int warpM = (wid >> 2) * 64;
    const int warpN = (wid & 3) * 32;
    const uint32_t aRow  = (uint32_t)(warpM + (lane & 15));
    const uint32_t aSegL = (uint32_t)(lane >> 4);
    const uint32_t bRow  = (uint32_t)(warpN + (lane & 7) + ((lane >> 4) & 1) * 8);
    const uint32_t bSegL = (uint32_t)((lane >> 3) & 1);

    float acc[4][4][4] = {};

    auto compute = [&](int stg) {
        const uint32_t base = sb + (uint32_t)stg * STAGE_BYTES;
        #pragma unroll
        for (int ks = 0; ks < 2; ks++) {
            uint32_t bw[2][4];
            #pragma unroll
            for (int g = 0; g < 2; g++) {
                const uint32_t bd = base + OFF_B
                                  + (bRow + g * 16) * ROW_PITCH
                                  + (ks * 2 + bSegL) * 16;
                ldsm4(bw[g], bd);
            }
            #pragma unroll
            for (int mf = 0; mf < 4; mf++) {
                uint32_t af[4];
                const uint32_t ad = base + OFF_A
                                  + (aRow + mf * 16) * ROW_PITCH
                                  + (ks * 2 + aSegL) * 16;
                ldsm4(af, ad);
                #pragma unroll
                for (int nf = 0; nf < 4; nf++)
                    mma16816(acc[mf][nf], af,
                             bw[nf >> 1][(nf & 1) * 2], bw[nf >> 1][(nf & 1) * 2 + 1]);
            }
        }
    };

    load_chunk(0, 0); CP_COMMIT();
    load_chunk(1, 1); CP_COMMIT();

    for (int c = 0; c < NCHUNK; c++) {
        cp_wait<1>();
        __syncthreads();
        if (c + 2 < NCHUNK) load_chunk(c + 2, (c + 2) % NSTAGE);
        CP_COMMIT();
        compute(c % NSTAGE);
    }

    #pragma unroll
    for (int mf = 0; mf < 4; mf++) {
        const int r0 = rowBase + warpM + mf * 16 + (lane >> 2);
        #pragma unroll
        for (int nf = 0; nf < 4; nf++) {
            const int cb = colBase + warpN + nf * 8 + (lane & 3) * 2;
            float2 lo, hi;
            lo.x = acc[mf][nf][0]; lo.y = acc[mf][nf][1];
            hi.x = acc[mf][nf][2]; hi.y = acc[mf][nf][3];
            if (cb >= sigStart) {
                lo.x = 1.0f / (1.0f + __expf(-lo.x));
                lo.y = 1.0f / (1.0f + __expf(-lo.y));
                hi.x = 1.0f / (1.0f + __expf(-hi.x));
                hi.y = 1.0f / (1.0f + __expf(-hi.y));
            }
            if constexpr (sizeof(OutT) == 2) {
                __half* Ch = (__half*)C;
                *(__half2*)(Ch + (size_t)r0 * ldc + cb) =
                    __floats2half2_rn(lo.x, lo.y);
                *(__half2*)(Ch + (size_t)(r0 + 8) * ldc + cb) =
                    __floats2half2_rn(hi.x, hi.y);
            } else {
                float* Cf = (float*)C;
                *(float2*)(Cf + (size_t)r0 * ldc + cb)       = lo;
                *(float2*)(Cf + (size_t)(r0 + 8) * ldc + cb) = hi;
            }
        }
    }
}

// ---------------------------------------------------------------------------
// Elementwise converts: fp32 -> fp16
// ---------------------------------------------------------------------------
__global__ void xconv_kernel(const float* __restrict__ src,
                             __half* __restrict__ dst, int n4)
{
    int i = blockIdx.x * blockDim.x + threadIdx.x;
    if (i >= n4) return;
    float4 v = ((const float4*)src)[i];
    __half h[4];
    h[0] = __float2half(v.x); h[1] = __float2half(v.y);
    h[2] = __float2half(v.z); h[3] = __float2half(v.w);
    ((uint2*)dst)[i] = *(uint2*)h;
}

__global__ void wconv_kernel(const float* __restrict__ w0, const float* __restrict__ w1,
                             const float* __restrict__ w2, const float* __restrict__ w3,
                             __half* __restrict__ w16, int n4)
{
    int i = blockIdx.x * blockDim.x + threadIdx.x;
    if (i >= n4) return;
    const float* src = (blockIdx.y == 0) ? w0 : (blockIdx.y == 1) ? w1
                     : (blockIdx.y == 2) ? w2 : w3;
    const size_t off = (size_t)blockIdx.y * (CDIM * CDIM / 4);
    float4 v = ((const float4*)src)[i];
    __half h[4];
    h[0] = __float2half(v.x); h[1] = __float2half(v.y);
    h[2] = __float2half(v.z); h[3] = __float2half(v.w);
    ((uint2*)w16)[off + i] = *(uint2*)h;
}

// ---------------------------------------------------------------------------
// WKV parallel scan (unnormalized, 1 exp/step). k|v|sr fused fp16 buffer:
// (b,t,c): k = kvr[(b*T+t)*2304 + c], v = +768, sr = +1536.
// ---------------------------------------------------------------------------
#define WKV_U 8

__device__ __forceinline__ void wkv_load3(
    const __half* __restrict__ kp, size_t base,
    float (&kb)[WKV_U], float (&vb)[WKV_U])
{
    #pragma unroll
    for (int i = 0; i < WKV_U; i++) {
        kb[i] = __half2float(kp[base + (size_t)i * ROWS3]);
        vb[i] = __half2float(kp[base + (size_t)i * ROWS3 + CDIM]);
    }
}

__global__ void __launch_bounds__(256) wkv_phase1(
    const __half* __restrict__ kvr,
    const float* __restrict__ sd, float* __restrict__ agg)
{
    const int gid  = blockIdx.x * blockDim.x + threadIdx.x;
    const int lane = gid % LANES;
    const int seg  = gid / LANES;
    const int b = lane / CDIM, c = lane % CDIM;

    const float ew = __expf(sd[c] * (1.0f / (float)TLEN));
    const __half* kp = kvr + ((size_t)b * TLEN + (size_t)seg * SEGLEN) * ROWS3 + c;

    float A = 0.0f, Bs = 0.0f;
    float k0b[WKV_U], v0b[WKV_U], k1b[WKV_U], v1b[WKV_U];
    wkv_load3(kp, 0, k0b, v0b);

    constexpr int NG = SEGLEN / WKV_U;   // 32
    for (int g = 0; g < NG; g += 2) {
        wkv_load3(kp, (size_t)(g + 1) * WKV_U * ROWS3, k1b, v1b);
        #pragma unroll
        for (int i = 0; i < WKV_U; i++) {
            const float ek = __expf(k0b[i]);
            A  = fmaf(ew, A,  ek * v0b[i]);
            Bs = fmaf(ew, Bs, ek);
        }
        if (g + 2 < NG)
            wkv_load3(kp, (size_t)(g + 2) * WKV_U * ROWS3, k0b, v0b);
        #pragma unroll
        for (int i = 0; i < WKV_U; i++) {
            const float ek = __expf(k1b[i]);
            A  = fmaf(ew, A,  ek * v1b[i]);
            Bs = fmaf(ew, Bs, ek);
        }
    }
    agg[0 * SEGTOT + gid] = A;
    agg[1 * SEGTOT + gid] = Bs;
}

__global__ void __launch_bounds__(256) wkv_phase2(
    const float* __restrict__ agg, const float* __restrict__ sd,
    float* __restrict__ pref)
{
    const int lane = blockIdx.x * blockDim.x + threadIdx.x;
    const int c = lane % CDIM;
    const float ewseg = __expf(sd[c] * ((float)SEGLEN / (float)TLEN));

    float A = 0.0f, Bs = 0.0f;
    #pragma unroll
    for (int s = 0; s < NSEG; s++) {
        const int idx = s * LANES + lane;
        pref[0 * SEGTOT + idx] = A;
        pref[1 * SEGTOT + idx] = Bs;
        A  = fmaf(ewseg, A,  agg[0 * SEGTOT + idx]);
        Bs = fmaf(ewseg, Bs, agg[1 * SEGTOT + idx]);
    }
}

// Phase 3: replay segments; emit m = sigmoid(r)*y directly as fp16
__global__ void __launch_bounds__(256) wkv_phase3(
    const __half* __restrict__ kvr,
    const float* __restrict__ sd, const float* __restrict__ sf,
    const float* __restrict__ pref,
    __half* __restrict__ mh)
{
    const int gid  = blockIdx.x * blockDim.x + threadIdx.x;
    const int lane = gid % LANES;
    const int seg  = gid / LANES;
    const int b = lane / CDIM, c = lane % CDIM;

    const float ew = __expf(sd[c] * (1.0f / (float)TLEN));
    const float eu = __expf(sf[c] * (1.0f / (float)TLEN));
    const size_t trow = (size_t)b * TLEN + (size_t)seg * SEGLEN;
    const __half* kp = kvr + trow * ROWS3 + c;
    __half* hp = mh + trow * CDIM + c;

    float A  = pref[0 * SEGTOT + gid];
    float Bs = pref[1 * SEGTOT + gid];

    float k0b[WKV_U], v0b[WKV_U], r0b[WKV_U];
    float k1b[WKV_U], v1b[WKV_U], r1b[WKV_U];
    wkv_load3(kp, 0, k0b, v0b);
    #pragma unroll
    for (int i = 0; i < WKV_U; i++)
        r0b[i] = __half2float(kp[(size_t)i * ROWS3 + 2 * CDIM]);

    auto emit = [&](const float (&kb)[WKV_U], const float (&vb)[WKV_U],
                    const float (&rb)[WKV_U], size_t tofs) {
        #pragma unroll
        for (int i = 0; i < WKV_U; i++) {
            const float ek  = __expf(kb[i]);
            const float euk = eu * ek;
            const float y = __fdividef(fmaf(euk, vb[i], A), Bs + euk);
            hp[(tofs + i) * CDIM] = __float2half(y * rb[i]);
            A  = fmaf(ew, A,  ek * vb[i]);
            Bs = fmaf(ew, Bs, ek);
        }
    };

    constexpr int NG = SEGLEN / WKV_U;
    for (int g = 0; g < NG; g += 2) {
        wkv_load3(kp, (size_t)(g + 1) * WKV_U * ROWS3, k1b, v1b);
        #pragma unroll
        for (int i = 0; i < WKV_U; i++)
            r1b[i] = __half2float(kp[((size_t)(g + 1) * WKV_U + i) * ROWS3 + 2 * CDIM]);
        emit(k0b, v0b, r0b, (size_t)g * WKV_U);
        if (g + 2 < NG) {
            wkv_load3(kp, (size_t)(g + 2) * WKV_U * ROWS3, k0b, v0b);
            #pragma unroll
            for (int i = 0; i < WKV_U; i++)
                r0b[i] = __half2float(kp[((size_t)(g + 2) * WKV_U + i) * ROWS3 + 2 * CDIM]);
        }
        emit(k1b, v1b, r1b, (size_t)(g + 1) * WKV_U);
    }
}

// ---------------------------------------------------------------------------
// Launch
// ---------------------------------------------------------------------------
extern "C" void kernel_launch(void* const* d_in, const int* in_sizes, int n_in,
                              void* d_out, int out_size)
{
    const float* x  = (const float*)d_in[0];
    const float* wk = (const float*)d_in[1];
    const float* wv = (const float*)d_in[2];
    const float* wr = (const float*)d_in[3];
    const float* wo = (const float*)d_in[4];
    const float* sd = (const float*)d_in[5];
    const float* sf = (const float*)d_in[6];
    float* out = (float*)d_out;

    float *gagg, *gpref;
    __half *gkvr, *a16, *w16;
    cudaGetSymbolAddress((void**)&gkvr, g_kvr);
    cudaGetSymbolAddress((void**)&gagg, g_agg);
    cudaGetSymbolAddress((void**)&gpref,g_pref);
    cudaGetSymbolAddress((void**)&a16,  g_a16);
    cudaGetSymbolAddress((void**)&w16,  g_w16);

    cudaFuncSetAttribute(gemm_hmma_kernel<__half>,
                         cudaFuncAttributeMaxDynamicSharedMemorySize, GEMM_SMEM);
    cudaFuncSetAttribute(gemm_hmma_kernel<float>,
                         cudaFuncAttributeMaxDynamicSharedMemorySize, GEMM_SMEM);

    const int nx4 = MROWS * CDIM / 4;
    const int nw4 = CDIM * CDIM / 4;

    xconv_kernel<<<(nx4 + 255) / 256, 256>>>(x, a16, nx4);
    {
        dim3 wg((nw4 + 255) / 256, 4);
        wconv_kernel<<<wg, 256>>>(wk, wv, wr, wo, w16, nw4);
    }

    // Fused k|v|sr projection (single product), fp16 out, sigmoid cols >= 1536
    {
        dim3 fgrid(ROWS3 / 128, MROWS / 128);   // (18, 256)
        gemm_hmma_kernel<__half><<<fgrid, 256, GEMM_SMEM>>>(
            a16, w16, gkvr, ROWS3, 2 * CDIM);
    }

    // WKV scan + fused gate-mul; emits fp16 m into a16
    wkv_phase1<<<SEGTOT / 256, 256>>>(gkvr, sd, gagg);
    wkv_phase2<<<LANES / 256, 256>>>(gagg, sd, gpref);
    wkv_phase3<<<SEGTOT / 256, 256>>>(gkvr, sd, sf, gpref, a16);

    // Output GEMM: single product, fp32 out, N = 768
    {
        dim3 ogrid(CDIM / 128, MROWS / 128);    // (6, 256)
        gemm_hmma_kernel<float><<<ogrid, 256, GEMM_SMEM>>>(
            a16, w16 + 3 * (size_t)CDIM * CDIM, out, CDIM, 1 << 30);
    }
}

// round 11
// speedup vs baseline: 2.4170x; 1.0070x over previous
#include <cuda_runtime.h>
#include <cuda_fp16.h>
#include <cstdint>
#include <cstddef>

// Problem constants (B=8, T=4096, C=768)
#define BSZ  8
#define TLEN 4096
#define CDIM 768
#define MROWS (BSZ * TLEN)   // 32768
#define KDIM CDIM
#define ROWS3 (3 * CDIM)     // 2304 fused k|v|sr row

#define NSEG   64
#define SEGLEN (TLEN / NSEG)          // 64
#define LANES  (BSZ * CDIM)           // 6144
#define SEGTOT (LANES * NSEG)         // 393216

// ---------------- scratch (__device__ globals; no allocations allowed) -----
__device__ __align__(16) __half g_kvr[MROWS * ROWS3]; // fused k|v|sr, fp16
__device__ __align__(16) __half g_a16[MROWS * CDIM];  // activation fp16 (x, then m)
__device__ __align__(16) __half g_w16[4][CDIM * CDIM];// wk,wv,wr,wo fp16
__device__ __align__(16) float g_agg [2 * SEGTOT];
__device__ __align__(16) float g_pref[2 * SEGTOT];

// ---------------- PTX helpers (sm_80-baseline only) -------------------------
__device__ __forceinline__ uint32_t smem_to_u32(const void* p) {
    uint32_t a;
    asm("{ .reg .u64 t; cvta.to.shared.u64 t, %1; cvt.u32.u64 %0, t; }"
        : "=r"(a) : "l"(p));
    return a;
}

__device__ __forceinline__ void cp_async16(uint32_t dst, const void* src) {
    asm volatile("cp.async.cg.shared.global [%0], [%1], 16;"
                 :: "r"(dst), "l"(src) : "memory");
}
#define CP_COMMIT() asm volatile("cp.async.commit_group;" ::: "memory")
template<int N>
__device__ __forceinline__ void cp_wait() {
    asm volatile("cp.async.wait_group %0;" :: "n"(N) : "memory");
}

__device__ __forceinline__ void ldsm4(uint32_t (&r)[4], uint32_t addr) {
    asm volatile("ldmatrix.sync.aligned.m8n8.x4.shared.b16 {%0,%1,%2,%3}, [%4];"
                 : "=r"(r[0]), "=r"(r[1]), "=r"(r[2]), "=r"(r[3]) : "r"(addr));
}

__device__ __forceinline__ void mma16816(float (&d)[4], const uint32_t (&a)[4],
                                         uint32_t b0, uint32_t b1) {
    asm volatile(
        "mma.sync.aligned.m16n8k16.row.col.f32.f16.f16.f32 "
        "{%0,%1,%2,%3}, {%4,%5,%6,%7}, {%8,%9}, {%0,%1,%2,%3};"
        : "+f"(d[0]), "+f"(d[1]), "+f"(d[2]), "+f"(d[3])
        : "r"(a[0]), "r"(a[1]), "r"(a[2]), "r"(a[3]), "r"(b0), "r"(b1));
}

// ---------------------------------------------------------------------------
// HMMA GEMM: C[m,n] = sum_k A[m,k]*B[n,k], single fp16 product.
// CTA 128x128, warp tile 64x32 (8 warps), BK=32, 3-stage cp.async, 2 CTAs/SM.
// OutT = __half (fp16 store) or float; sigmoid on cols >= sigStart.
// ---------------------------------------------------------------------------
#define BKC 32
#define NCHUNK (KDIM / BKC)            // 24
#define ROW_PITCH 80
#define TILE_BYTES (128 * ROW_PITCH)   // 10240
#define OFF_A 0
#define OFF_B TILE_BYTES
#define STAGE_BYTES (2 * TILE_BYTES)   // 20480
#define NSTAGE 3
#define GEMM_SMEM (NSTAGE * STAGE_BYTES)  // 61440

template<typename OutT>
__global__ void __launch_bounds__(256, 2) gemm_hmma_kernel(
    const __half* __restrict__ Aa, const __half* __restrict__ Bw,
    OutT* __restrict__ C, int ldc, int sigStart)
{
    extern __shared__ char smem[];
    const uint32_t sb = smem_to_u32(smem);
    const int tid  = threadIdx.x;
    const int wid  = tid >> 5;
    const int lane = tid & 31;
    const int rowBase = blockIdx.y * 128;
    const int colBase = blockIdx.x * 128;

    const char* srcs[2] = {
        (const char*)(Aa + (size_t)rowBase * KDIM),
        (const char*)(Bw + (size_t)colBase * KDIM) };

    const int lr0 = tid >> 2;          // 0..63
    const int ls  = (tid & 3) * 16;
    auto load_chunk = [&](int c, int stg) {
        const size_t colOff = (size_t)c * (BKC * 2);
        const uint32_t stgb = sb + (uint32_t)stg * STAGE_BYTES;
        #pragma unroll
        for (int t = 0; t < 2; t++) {
            const char* srcb = srcs[t] + colOff;
            const uint32_t dstb = stgb + (uint32_t)t * TILE_BYTES;
            #pragma unroll
            for (int i = 0; i < 2; i++) {
                const int r = lr0 + i * 64;
                cp_async16(dstb + (uint32_t)(r * ROW_PITCH) + ls,
                           srcb + (size_t)r * (KDIM * 2) + ls);
            }
        }
    };

    const int warpM = (wid >> 2) * 64;
    const int warpN = (wid & 3) * 32;
    const uint32_t aRow  = (uint32_t)(warpM + (lane & 15));
    const uint32_t aSegL = (uint32_t)(lane >> 4);
    const uint32_t bRow  = (uint32_t)(warpN + (lane & 7) + ((lane >> 4) & 1) * 8);
    const uint32_t bSegL = (uint32_t)((lane >> 3) & 1);

    float acc[4][4][4] = {};

    auto compute = [&](int stg) {
        const uint32_t base = sb + (uint32_t)stg * STAGE_BYTES;
        #pragma unroll
        for (int ks = 0; ks < 2; ks++) {
            uint32_t bw[2][4];
            #pragma unroll
            for (int g = 0; g < 2; g++) {
                const uint32_t bd = base + OFF_B
                                  + (bRow + g * 16) * ROW_PITCH
                                  + (ks * 2 + bSegL) * 16;
                ldsm4(bw[g], bd);
            }
            #pragma unroll
            for (int mf = 0; mf < 4; mf++) {
                uint32_t af[4];
                const uint32_t ad = base + OFF_A
                                  + (aRow + mf * 16) * ROW_PITCH
                                  + (ks * 2 + aSegL) * 16;
                ldsm4(af, ad);
                #pragma unroll
                for (int nf = 0; nf < 4; nf++)
                    mma16816(acc[mf][nf], af,
                             bw[nf >> 1][(nf & 1) * 2], bw[nf >> 1][(nf & 1) * 2 + 1]);
            }
        }
    };

    load_chunk(0, 0); CP_COMMIT();
    load_chunk(1, 1); CP_COMMIT();

    for (int c = 0; c < NCHUNK; c++) {
        cp_wait<1>();
        __syncthreads();
        if (c + 2 < NCHUNK) load_chunk(c + 2, (c + 2) % NSTAGE);
        CP_COMMIT();
        compute(c % NSTAGE);
    }

    #pragma unroll
    for (int mf = 0; mf < 4; mf++) {
        const int r0 = rowBase + warpM + mf * 16 + (lane >> 2);
        #pragma unroll
        for (int nf = 0; nf < 4; nf++) {
            const int cb = colBase + warpN + nf * 8 + (lane & 3) * 2;
            float2 lo, hi;
            lo.x = acc[mf][nf][0]; lo.y = acc[mf][nf][1];
            hi.x = acc[mf][nf][2]; hi.y = acc[mf][nf][3];
            if (cb >= sigStart) {
                lo.x = 1.0f / (1.0f + __expf(-lo.x));
                lo.y = 1.0f / (1.0f + __expf(-lo.y));
                hi.x = 1.0f / (1.0f + __expf(-hi.x));
                hi.y = 1.0f / (1.0f + __expf(-hi.y));
            }
            if constexpr (sizeof(OutT) == 2) {
                __half* Ch = (__half*)C;
                *(__half2*)(Ch + (size_t)r0 * ldc + cb) =
                    __floats2half2_rn(lo.x, lo.y);
                *(__half2*)(Ch + (size_t)(r0 + 8) * ldc + cb) =
                    __floats2half2_rn(hi.x, hi.y);
            } else {
                float* Cf = (float*)C;
                *(float2*)(Cf + (size_t)r0 * ldc + cb)       = lo;
                *(float2*)(Cf + (size_t)(r0 + 8) * ldc + cb) = hi;
            }
        }
    }
}

// ---------------------------------------------------------------------------
// Elementwise converts: fp32 -> fp16
// ---------------------------------------------------------------------------
__global__ void xconv_kernel(const float* __restrict__ src,
                             __half* __restrict__ dst, int n4)
{
    int i = blockIdx.x * blockDim.x + threadIdx.x;
    if (i >= n4) return;
    float4 v = ((const float4*)src)[i];
    __half h[4];
    h[0] = __float2half(v.x); h[1] = __float2half(v.y);
    h[2] = __float2half(v.z); h[3] = __float2half(v.w);
    ((uint2*)dst)[i] = *(uint2*)h;
}

__global__ void wconv_kernel(const float* __restrict__ w0, const float* __restrict__ w1,
                             const float* __restrict__ w2, const float* __restrict__ w3,
                             __half* __restrict__ w16, int n4)
{
    int i = blockIdx.x * blockDim.x + threadIdx.x;
    if (i >= n4) return;
    const float* src = (blockIdx.y == 0) ? w0 : (blockIdx.y == 1) ? w1
                     : (blockIdx.y == 2) ? w2 : w3;
    const size_t off = (size_t)blockIdx.y * (CDIM * CDIM / 4);
    float4 v = ((const float4*)src)[i];
    __half h[4];
    h[0] = __float2half(v.x); h[1] = __float2half(v.y);
    h[2] = __float2half(v.z); h[3] = __float2half(v.w);
    ((uint2*)w16)[off + i] = *(uint2*)h;
}

// ---------------------------------------------------------------------------
// WKV parallel scan (unnormalized, 1 exp/step). k|v|sr fused fp16 buffer:
// (b,t,c): k = kvr[(b*T+t)*2304 + c], v = +768, sr = +1536.
// NSEG=64 segments of 64 steps: phase1/3 grids = 1536 CTAs (10.4/SM).
// ---------------------------------------------------------------------------
#define WKV_U 8

__device__ __forceinline__ void wkv_load3(
    const __half* __restrict__ kp, size_t base,
    float (&kb)[WKV_U], float (&vb)[WKV_U])
{
    #pragma unroll
    for (int i = 0; i < WKV_U; i++) {
        kb[i] = __half2float(kp[base + (size_t)i * ROWS3]);
        vb[i] = __half2float(kp[base + (size_t)i * ROWS3 + CDIM]);
    }
}

__global__ void __launch_bounds__(256) wkv_phase1(
    const __half* __restrict__ kvr,
    const float* __restrict__ sd, float* __restrict__ agg)
{
    const int gid  = blockIdx.x * blockDim.x + threadIdx.x;
    const int lane = gid % LANES;
    const int seg  = gid / LANES;
    const int b = lane / CDIM, c = lane % CDIM;

    const float ew = __expf(sd[c] * (1.0f / (float)TLEN));
    const __half* kp = kvr + ((size_t)b * TLEN + (size_t)seg * SEGLEN) * ROWS3 + c;

    float A = 0.0f, Bs = 0.0f;
    float k0b[WKV_U], v0b[WKV_U], k1b[WKV_U], v1b[WKV_U];
    wkv_load3(kp, 0, k0b, v0b);

    constexpr int NG = SEGLEN / WKV_U;   // 8
    for (int g = 0; g < NG; g += 2) {
        wkv_load3(kp, (size_t)(g + 1) * WKV_U * ROWS3, k1b, v1b);
        #pragma unroll
        for (int i = 0; i < WKV_U; i++) {
            const float ek = __expf(k0b[i]);
            A  = fmaf(ew, A,  ek * v0b[i]);
            Bs = fmaf(ew, Bs, ek);
        }
        if (g + 2 < NG)
            wkv_load3(kp, (size_t)(g + 2) * WKV_U * ROWS3, k0b, v0b);
        #pragma unroll
        for (int i = 0; i < WKV_U; i++) {
            const float ek = __expf(k1b[i]);
            A  = fmaf(ew, A,  ek * v1b[i]);
            Bs = fmaf(ew, Bs, ek);
        }
    }
    agg[0 * SEGTOT + gid] = A;
    agg[1 * SEGTOT + gid] = Bs;
}

__global__ void __launch_bounds__(256) wkv_phase2(
    const float* __restrict__ agg, const float* __restrict__ sd,
    float* __restrict__ pref)
{
    const int lane = blockIdx.x * blockDim.x + threadIdx.x;
    const int c = lane % CDIM;
    const float ewseg = __expf(sd[c] * ((float)SEGLEN / (float)TLEN));

    float A = 0.0f, Bs = 0.0f;
    #pragma unroll 8
    for (int s = 0; s < NSEG; s++) {
        const int idx = s * LANES + lane;
        pref[0 * SEGTOT + idx] = A;
        pref[1 * SEGTOT + idx] = Bs;
        A  = fmaf(ewseg, A,  agg[0 * SEGTOT + idx]);
        Bs = fmaf(ewseg, Bs, agg[1 * SEGTOT + idx]);
    }
}

// Phase 3: replay segments; emit m = sigmoid(r)*y directly as fp16
__global__ void __launch_bounds__(256) wkv_phase3(
    const __half* __restrict__ kvr,
    const float* __restrict__ sd, const float* __restrict__ sf,
    const float* __restrict__ pref,
    __half* __restrict__ mh)
{
    const int gid  = blockIdx.x * blockDim.x + threadIdx.x;
    const int lane = gid % LANES;
    const int seg  = gid / LANES;
    const int b = lane / CDIM, c = lane % CDIM;

    const float ew = __expf(sd[c] * (1.0f / (float)TLEN));
    const float eu = __expf(sf[c] * (1.0f / (float)TLEN));
    const size_t trow = (size_t)b * TLEN + (size_t)seg * SEGLEN;
    const __half* kp = kvr + trow * ROWS3 + c;
    __half* hp = mh + trow * CDIM + c;

    float A  = pref[0 * SEGTOT + gid];
    float Bs = pref[1 * SEGTOT + gid];

    float k0b[WKV_U], v0b[WKV_U], r0b[WKV_U];
    float k1b[WKV_U], v1b[WKV_U], r1b[WKV_U];
    wkv_load3(kp, 0, k0b, v0b);
    #pragma unroll
    for (int i = 0; i < WKV_U; i++)
        r0b[i] = __half2float(kp[(size_t)i * ROWS3 + 2 * CDIM]);

    auto emit = [&](const float (&kb)[WKV_U], const float (&vb)[WKV_U],
                    const float (&rb)[WKV_U], size_t tofs) {
        #pragma unroll
        for (int i = 0; i < WKV_U; i++) {
            const float ek  = __expf(kb[i]);
            const float euk = eu * ek;
            const float y = __fdividef(fmaf(euk, vb[i], A), Bs + euk);
            hp[(tofs + i) * CDIM] = __float2half(y * rb[i]);
            A  = fmaf(ew, A,  ek * vb[i]);
            Bs = fmaf(ew, Bs, ek);
        }
    };

    constexpr int NG = SEGLEN / WKV_U;   // 8
    for (int g = 0; g < NG; g += 2) {
        wkv_load3(kp, (size_t)(g + 1) * WKV_U * ROWS3, k1b, v1b);
        #pragma unroll
        for (int i = 0; i < WKV_U; i++)
            r1b[i] = __half2float(kp[((size_t)(g + 1) * WKV_U + i) * ROWS3 + 2 * CDIM]);
        emit(k0b, v0b, r0b, (size_t)g * WKV_U);
        if (g + 2 < NG) {
            wkv_load3(kp, (size_t)(g + 2) * WKV_U * ROWS3, k0b, v0b);
            #pragma unroll
            for (int i = 0; i < WKV_U; i++)
                r0b[i] = __half2float(kp[((size_t)(g + 2) * WKV_U + i) * ROWS3 + 2 * CDIM]);
        }
        emit(k1b, v1b, r1b, (size_t)(g + 1) * WKV_U);
    }
}

// ---------------------------------------------------------------------------
// Launch
// ---------------------------------------------------------------------------
extern "C" void kernel_launch(void* const* d_in, const int* in_sizes, int n_in,
                              void* d_out, int out_size)
{
    const float* x  = (const float*)d_in[0];
    const float* wk = (const float*)d_in[1];
    const float* wv = (const float*)d_in[2];
    const float* wr = (const float*)d_in[3];
    const float* wo = (const float*)d_in[4];
    const float* sd = (const float*)d_in[5];
    const float* sf = (const float*)d_in[6];
    float* out = (float*)d_out;

    float *gagg, *gpref;
    __half *gkvr, *a16, *w16;
    cudaGetSymbolAddress((void**)&gkvr, g_kvr);
    cudaGetSymbolAddress((void**)&gagg, g_agg);
    cudaGetSymbolAddress((void**)&gpref,g_pref);
    cudaGetSymbolAddress((void**)&a16,  g_a16);
    cudaGetSymbolAddress((void**)&w16,  g_w16);

    cudaFuncSetAttribute(gemm_hmma_kernel<__half>,
                         cudaFuncAttributeMaxDynamicSharedMemorySize, GEMM_SMEM);
    cudaFuncSetAttribute(gemm_hmma_kernel<float>,
                         cudaFuncAttributeMaxDynamicSharedMemorySize, GEMM_SMEM);

    const int nx4 = MROWS * CDIM / 4;
    const int nw4 = CDIM * CDIM / 4;

    xconv_kernel<<<(nx4 + 255) / 256, 256>>>(x, a16, nx4);
    {
        dim3 wg((nw4 + 255) / 256, 4);
        wconv_kernel<<<wg, 256>>>(wk, wv, wr, wo, w16, nw4);
    }

    // Fused k|v|sr projection (single product), fp16 out, sigmoid cols >= 1536
    {
        dim3 fgrid(ROWS3 / 128, MROWS / 128);   // (18, 256)
        gemm_hmma_kernel<__half><<<fgrid, 256, GEMM_SMEM>>>(
            a16, w16, gkvr, ROWS3, 2 * CDIM);
    }

    // WKV scan + fused gate-mul; emits fp16 m into a16
    wkv_phase1<<<SEGTOT / 256, 256>>>(gkvr, sd, gagg);   // 1536 CTAs
    wkv_phase2<<<LANES / 256, 256>>>(gagg, sd, gpref);
    wkv_phase3<<<SEGTOT / 256, 256>>>(gkvr, sd, sf, gpref, a16);  // 1536 CTAs

    // Output GEMM: single product, fp32 out, N = 768
    {
        dim3 ogrid(CDIM / 128, MROWS / 128);    // (6, 256)
        gemm_hmma_kernel<float><<<ogrid, 256, GEMM_SMEM>>>(
            a16, w16 + 3 * (size_t)CDIM * CDIM, out, CDIM, 1 << 30);
    }
}

// round 12
// speedup vs baseline: 2.4755x; 1.0242x over previous
#include <cuda_runtime.h>
#include <cuda_fp16.h>
#include <cstdint>
#include <cstddef>

// Problem constants (B=8, T=4096, C=768)
#define BSZ  8
#define TLEN 4096
#define CDIM 768
#define MROWS (BSZ * TLEN)   // 32768
#define KDIM CDIM
#define ROWS3 (3 * CDIM)     // 2304 fused k|v|sr row

#define NSEG   64
#define SEGLEN (TLEN / NSEG)          // 64
#define LANES  (BSZ * CDIM)           // 6144
#define SEGTOT (LANES * NSEG)         // 393216
#define LANES2 (LANES / 2)            // 3072 channel-pairs
#define SEGTOT2 (SEGTOT / 2)          // 196608

// ---------------- scratch (__device__ globals; no allocations allowed) -----
__device__ __align__(16) __half g_kvr[MROWS * ROWS3]; // fused k|v|sr, fp16
__device__ __align__(16) __half g_a16[MROWS * CDIM];  // activation fp16 (x, then m)
__device__ __align__(16) __half g_w16[4][CDIM * CDIM];// wk,wv,wr,wo fp16
__device__ __align__(16) float g_agg [2 * SEGTOT];
__device__ __align__(16) float g_pref[2 * SEGTOT];

// ---------------- PTX helpers (sm_80-baseline only) -------------------------
__device__ __forceinline__ uint32_t smem_to_u32(const void* p) {
    uint32_t a;
    asm("{ .reg .u64 t; cvta.to.shared.u64 t, %1; cvt.u32.u64 %0, t; }"
        : "=r"(a) : "l"(p));
    return a;
}

__device__ __forceinline__ void cp_async16(uint32_t dst, const void* src) {
    asm volatile("cp.async.cg.shared.global [%0], [%1], 16;"
                 :: "r"(dst), "l"(src) : "memory");
}
#define CP_COMMIT() asm volatile("cp.async.commit_group;" ::: "memory")
template<int N>
__device__ __forceinline__ void cp_wait() {
    asm volatile("cp.async.wait_group %0;" :: "n"(N) : "memory");
}

__device__ __forceinline__ void ldsm4(uint32_t (&r)[4], uint32_t addr) {
    asm volatile("ldmatrix.sync.aligned.m8n8.x4.shared.b16 {%0,%1,%2,%3}, [%4];"
                 : "=r"(r[0]), "=r"(r[1]), "=r"(r[2]), "=r"(r[3]) : "r"(addr));
}

__device__ __forceinline__ void mma16816(float (&d)[4], const uint32_t (&a)[4],
                                         uint32_t b0, uint32_t b1) {
    asm volatile(
        "mma.sync.aligned.m16n8k16.row.col.f32.f16.f16.f32 "
        "{%0,%1,%2,%3}, {%4,%5,%6,%7}, {%8,%9}, {%0,%1,%2,%3};"
        : "+f"(d[0]), "+f"(d[1]), "+f"(d[2]), "+f"(d[3])
        : "r"(a[0]), "r"(a[1]), "r"(a[2]), "r"(a[3]), "r"(b0), "r"(b1));
}

// ---------------------------------------------------------------------------
// HMMA GEMM: C[m,n] = sum_k A[m,k]*B[n,k], single fp16 product.
// CTA 128x128, warp tile 64x32 (8 warps), BK=32, 3-stage cp.async, 2 CTAs/SM.
// OutT = __half (fp16 store) or float; sigmoid on cols >= sigStart.
// (unchanged since R9: pinned at the legacy mma.sync issue floor)
// ---------------------------------------------------------------------------
#define BKC 32
#define NCHUNK (KDIM / BKC)            // 24
#define ROW_PITCH 80
#define TILE_BYTES (128 * ROW_PITCH)   // 10240
#define OFF_A 0
#define OFF_B TILE_BYTES
#define STAGE_BYTES (2 * TILE_BYTES)   // 20480
#define NSTAGE 3
#define GEMM_SMEM (NSTAGE * STAGE_BYTES)  // 61440

template<typename OutT>
__global__ void __launch_bounds__(256, 2) gemm_hmma_kernel(
    const __half* __restrict__ Aa, const __half* __restrict__ Bw,
    OutT* __restrict__ C, int ldc, int sigStart)
{
    extern __shared__ char smem[];
    const uint32_t sb = smem_to_u32(smem);
    const int tid  = threadIdx.x;
    const int wid  = tid >> 5;
    const int lane = tid & 31;
    const int rowBase = blockIdx.y * 128;
    const int colBase = blockIdx.x * 128;

    const char* srcs[2] = {
        (const char*)(Aa + (size_t)rowBase * KDIM),
        (const char*)(Bw + (size_t)colBase * KDIM) };

    const int lr0 = tid >> 2;          // 0..63
    const int ls  = (tid & 3) * 16;
    auto load_chunk = [&](int c, int stg) {
        const size_t colOff = (size_t)c * (BKC * 2);
        const uint32_t stgb = sb + (uint32_t)stg * STAGE_BYTES;
        #pragma unroll
        for (int t = 0; t < 2; t++) {
            const char* srcb = srcs[t] + colOff;
            const uint32_t dstb = stgb + (uint32_t)t * TILE_BYTES;
            #pragma unroll
            for (int i = 0; i < 2; i++) {
                const int r = lr0 + i * 64;
                cp_async16(dstb + (uint32_t)(r * ROW_PITCH) + ls,
                           srcb + (size_t)r * (KDIM * 2) + ls);
            }
        }
    };

    const int warpM = (wid >> 2) * 64;
    const int warpN = (wid & 3) * 32;
    const uint32_t aRow  = (uint32_t)(warpM + (lane & 15));
    const uint32_t aSegL = (uint32_t)(lane >> 4);
    const uint32_t bRow  = (uint32_t)(warpN + (lane & 7) + ((lane >> 4) & 1) * 8);
    const uint32_t bSegL = (uint32_t)((lane >> 3) & 1);

    float acc[4][4][4] = {};

    auto compute = [&](int stg) {
        const uint32_t base = sb + (uint32_t)stg * STAGE_BYTES;
        #pragma unroll
        for (int ks = 0; ks < 2; ks++) {
            uint32_t bw[2][4];
            #pragma unroll
            for (int g = 0; g < 2; g++) {
                const uint32_t bd = base + OFF_B
                                  + (bRow + g * 16) * ROW_PITCH
                                  + (ks * 2 + bSegL) * 16;
                ldsm4(bw[g], bd);
            }
            #pragma unroll
            for (int mf = 0; mf < 4; mf++) {
                uint32_t af[4];
                const uint32_t ad = base + OFF_A
                                  + (aRow + mf * 16) * ROW_PITCH
                                  + (ks * 2 + aSegL) * 16;
                ldsm4(af, ad);
                #pragma unroll
                for (int nf = 0; nf < 4; nf++)
                    mma16816(acc[mf][nf], af,
                             bw[nf >> 1][(nf & 1) * 2], bw[nf >> 1][(nf & 1) * 2 + 1]);
            }
        }
    };

    load_chunk(0, 0); CP_COMMIT();
    load_chunk(1, 1); CP_COMMIT();

    for (int c = 0; c < NCHUNK; c++) {
        cp_wait<1>();
        __syncthreads();
        if (c + 2 < NCHUNK) load_chunk(c + 2, (c + 2) % NSTAGE);
        CP_COMMIT();
        compute(c % NSTAGE);
    }

    #pragma unroll
    for (int mf = 0; mf < 4; mf++) {
        const int r0 = rowBase + warpM + mf * 16 + (lane >> 2);
        #pragma unroll
        for (int nf = 0; nf < 4; nf++) {
            const int cb = colBase + warpN + nf * 8 + (lane & 3) * 2;
            float2 lo, hi;
            lo.x = acc[mf][nf][0]; lo.y = acc[mf][nf][1];
            hi.x = acc[mf][nf][2]; hi.y = acc[mf][nf][3];
            if (cb >= sigStart) {
                lo.x = 1.0f / (1.0f + __expf(-lo.x));
                lo.y = 1.0f / (1.0f + __expf(-lo.y));
                hi.x = 1.0f / (1.0f + __expf(-hi.x));
                hi.y = 1.0f / (1.0f + __expf(-hi.y));
            }
            if constexpr (sizeof(OutT) == 2) {
                __half* Ch = (__half*)C;
                *(__half2*)(Ch + (size_t)r0 * ldc + cb) =
                    __floats2half2_rn(lo.x, lo.y);
                *(__half2*)(Ch + (size_t)(r0 + 8) * ldc + cb) =
                    __floats2half2_rn(hi.x, hi.y);
            } else {
                float* Cf = (float*)C;
                *(float2*)(Cf + (size_t)r0 * ldc + cb)       = lo;
                *(float2*)(Cf + (size_t)(r0 + 8) * ldc + cb) = hi;
            }
        }
    }
}

// ---------------------------------------------------------------------------
// Elementwise converts: fp32 -> fp16
// ---------------------------------------------------------------------------
__global__ void xconv_kernel(const float* __restrict__ src,
                             __half* __restrict__ dst, int n4)
{
    int i = blockIdx.x * blockDim.x + threadIdx.x;
    if (i >= n4) return;
    float4 v = ((const float4*)src)[i];
    __half h[4];
    h[0] = __float2half(v.x); h[1] = __float2half(v.y);
    h[2] = __float2half(v.z); h[3] = __float2half(v.w);
    ((uint2*)dst)[i] = *(uint2*)h;
}

__global__ void wconv_kernel(const float* __restrict__ w0, const float* __restrict__ w1,
                             const float* __restrict__ w2, const float* __restrict__ w3,
                             __half* __restrict__ w16, int n4)
{
    int i = blockIdx.x * blockDim.x + threadIdx.x;
    if (i >= n4) return;
    const float* src = (blockIdx.y == 0) ? w0 : (blockIdx.y == 1) ? w1
                     : (blockIdx.y == 2) ? w2 : w3;
    const size_t off = (size_t)blockIdx.y * (CDIM * CDIM / 4);
    float4 v = ((const float4*)src)[i];
    __half h[4];
    h[0] = __float2half(v.x); h[1] = __float2half(v.y);
    h[2] = __float2half(v.z); h[3] = __float2half(v.w);
    ((uint2*)w16)[off + i] = *(uint2*)h;
}

// ---------------------------------------------------------------------------
// WKV parallel scan (unnormalized, 1 exp/step), __half2 channel-pairing:
// each thread handles channels (c0, c0+1) -> 4B coalesced loads, full lines.
// kvr layout (b,t,c): k = kvr[(b*T+t)*2304 + c], v = +768, sr = +1536.
// ---------------------------------------------------------------------------
#define WKV_U 8

__device__ __forceinline__ void wkv_load3v(
    const __half* __restrict__ kp, size_t base,
    uint32_t (&kb)[WKV_U], uint32_t (&vb)[WKV_U])
{
    #pragma unroll
    for (int i = 0; i < WKV_U; i++) {
        kb[i] = *(const uint32_t*)(kp + base + (size_t)i * ROWS3);
        vb[i] = *(const uint32_t*)(kp + base + (size_t)i * ROWS3 + CDIM);
    }
}

__global__ void __launch_bounds__(256) wkv_phase1(
    const __half* __restrict__ kvr,
    const float* __restrict__ sd, float* __restrict__ agg)
{
    const int gid   = blockIdx.x * blockDim.x + threadIdx.x;   // 0..SEGTOT2-1
    const int lane2 = gid % LANES2;
    const int seg   = gid / LANES2;
    const int b  = lane2 / (CDIM / 2);
    const int c0 = (lane2 % (CDIM / 2)) * 2;

    const float ew0 = __expf(sd[c0]     * (1.0f / (float)TLEN));
    const float ew1 = __expf(sd[c0 + 1] * (1.0f / (float)TLEN));
    const __half* kp = kvr + ((size_t)b * TLEN + (size_t)seg * SEGLEN) * ROWS3 + c0;

    float A0 = 0.0f, B0 = 0.0f, A1 = 0.0f, B1 = 0.0f;
    uint32_t k0b[WKV_U], v0b[WKV_U], k1b[WKV_U], v1b[WKV_U];
    wkv_load3v(kp, 0, k0b, v0b);

    auto step8 = [&](const uint32_t (&kb)[WKV_U], const uint32_t (&vb)[WKV_U]) {
        #pragma unroll
        for (int i = 0; i < WKV_U; i++) {
            const float2 kf = __half22float2(*(const __half2*)&kb[i]);
            const float2 vf = __half22float2(*(const __half2*)&vb[i]);
            const float e0 = __expf(kf.x);
            const float e1 = __expf(kf.y);
            A0 = fmaf(ew0, A0, e0 * vf.x);  B0 = fmaf(ew0, B0, e0);
            A1 = fmaf(ew1, A1, e1 * vf.y);  B1 = fmaf(ew1, B1, e1);
        }
    };

    constexpr int NG = SEGLEN / WKV_U;   // 8
    for (int g = 0; g < NG; g += 2) {
        wkv_load3v(kp, (size_t)(g + 1) * WKV_U * ROWS3, k1b, v1b);
        step8(k0b, v0b);
        if (g + 2 < NG)
            wkv_load3v(kp, (size_t)(g + 2) * WKV_U * ROWS3, k0b, v0b);
        step8(k1b, v1b);
    }

    const int idx = seg * LANES + b * CDIM + c0;   // even -> 8B aligned
    *(float2*)&agg[0 * SEGTOT + idx] = make_float2(A0, A1);
    *(float2*)&agg[1 * SEGTOT + idx] = make_float2(B0, B1);
}

__global__ void __launch_bounds__(256) wkv_phase2(
    const float* __restrict__ agg, const float* __restrict__ sd,
    float* __restrict__ pref)
{
    const int lane = blockIdx.x * blockDim.x + threadIdx.x;
    const int c = lane % CDIM;
    const float ewseg = __expf(sd[c] * ((float)SEGLEN / (float)TLEN));

    float A = 0.0f, Bs = 0.0f;
    #pragma unroll 8
    for (int s = 0; s < NSEG; s++) {
        const int idx = s * LANES + lane;
        pref[0 * SEGTOT + idx] = A;
        pref[1 * SEGTOT + idx] = Bs;
        A  = fmaf(ewseg, A,  agg[0 * SEGTOT + idx]);
        Bs = fmaf(ewseg, Bs, agg[1 * SEGTOT + idx]);
    }
}

// Phase 3: replay segments; emit m = sigmoid(r)*y as __half2
__global__ void __launch_bounds__(256) wkv_phase3(
    const __half* __restrict__ kvr,
    const float* __restrict__ sd, const float* __restrict__ sf,
    const float* __restrict__ pref,
    __half* __restrict__ mh)
{
    const int gid   = blockIdx.x * blockDim.x + threadIdx.x;   // 0..SEGTOT2-1
    const int lane2 = gid % LANES2;
    const int seg   = gid / LANES2;
    const int b  = lane2 / (CDIM / 2);
    const int c0 = (lane2 % (CDIM / 2)) * 2;

    const float ew0 = __expf(sd[c0]     * (1.0f / (float)TLEN));
    const float ew1 = __expf(sd[c0 + 1] * (1.0f / (float)TLEN));
    const float eu0 = __expf(sf[c0]     * (1.0f / (float)TLEN));
    const float eu1 = __expf(sf[c0 + 1] * (1.0f / (float)TLEN));
    const size_t trow = (size_t)b * TLEN + (size_t)seg * SEGLEN;
    const __half* kp = kvr + trow * ROWS3 + c0;
    __half* hp = mh + trow * CDIM + c0;

    const int pidx = seg * LANES + b * CDIM + c0;
    const float2 Ap = *(const float2*)&pref[0 * SEGTOT + pidx];
    const float2 Bp = *(const float2*)&pref[1 * SEGTOT + pidx];
    float A0 = Ap.x, A1 = Ap.y, B0 = Bp.x, B1 = Bp.y;

    uint32_t k0b[WKV_U], v0b[WKV_U], r0b[WKV_U];
    uint32_t k1b[WKV_U], v1b[WKV_U], r1b[WKV_U];
    wkv_load3v(kp, 0, k0b, v0b);
    #pragma unroll
    for (int i = 0; i < WKV_U; i++)
        r0b[i] = *(const uint32_t*)(kp + (size_t)i * ROWS3 + 2 * CDIM);

    auto emit = [&](const uint32_t (&kb)[WKV_U], const uint32_t (&vb)[WKV_U],
                    const uint32_t (&rb)[WKV_U], size_t tofs) {
        #pragma unroll
        for (int i = 0; i < WKV_U; i++) {
            const float2 kf = __half22float2(*(const __half2*)&kb[i]);
            const float2 vf = __half22float2(*(const __half2*)&vb[i]);
            const float2 rf = __half22float2(*(const __half2*)&rb[i]);
            const float e0 = __expf(kf.x);
            const float e1 = __expf(kf.y);
            const float euk0 = eu0 * e0;
            const float euk1 = eu1 * e1;
            const float y0 = __fdividef(fmaf(euk0, vf.x, A0), B0 + euk0);
            const float y1 = __fdividef(fmaf(euk1, vf.y, A1), B1 + euk1);
            *(__half2*)(hp + (tofs + i) * CDIM) =
                __floats2half2_rn(y0 * rf.x, y1 * rf.y);
            A0 = fmaf(ew0, A0, e0 * vf.x);  B0 = fmaf(ew0, B0, e0);
            A1 = fmaf(ew1, A1, e1 * vf.y);  B1 = fmaf(ew1, B1, e1);
        }
    };

    constexpr int NG = SEGLEN / WKV_U;   // 8
    for (int g = 0; g < NG; g += 2) {
        wkv_load3v(kp, (size_t)(g + 1) * WKV_U * ROWS3, k1b, v1b);
        #pragma unroll
        for (int i = 0; i < WKV_U; i++)
            r1b[i] = *(const uint32_t*)(kp + ((size_t)(g + 1) * WKV_U + i) * ROWS3 + 2 * CDIM);
        emit(k0b, v0b, r0b, (size_t)g * WKV_U);
        if (g + 2 < NG) {
            wkv_load3v(kp, (size_t)(g + 2) * WKV_U * ROWS3, k0b, v0b);
            #pragma unroll
            for (int i = 0; i < WKV_U; i++)
                r0b[i] = *(const uint32_t*)(kp + ((size_t)(g + 2) * WKV_U + i) * ROWS3 + 2 * CDIM);
        }
        emit(k1b, v1b, r1b, (size_t)(g + 1) * WKV_U);
    }
}

// ---------------------------------------------------------------------------
// Launch
// ---------------------------------------------------------------------------
extern "C" void kernel_launch(void* const* d_in, const int* in_sizes, int n_in,
                              void* d_out, int out_size)
{
    const float* x  = (const float*)d_in[0];
    const float* wk = (const float*)d_in[1];
    const float* wv = (const float*)d_in[2];
    const float* wr = (const float*)d_in[3];
    const float* wo = (const float*)d_in[4];
    const float* sd = (const float*)d_in[5];
    const float* sf = (const float*)d_in[6];
    float* out = (float*)d_out;

    float *gagg, *gpref;
    __half *gkvr, *a16, *w16;
    cudaGetSymbolAddress((void**)&gkvr, g_kvr);
    cudaGetSymbolAddress((void**)&gagg, g_agg);
    cudaGetSymbolAddress((void**)&gpref,g_pref);
    cudaGetSymbolAddress((void**)&a16,  g_a16);
    cudaGetSymbolAddress((void**)&w16,  g_w16);

    cudaFuncSetAttribute(gemm_hmma_kernel<__half>,
                         cudaFuncAttributeMaxDynamicSharedMemorySize, GEMM_SMEM);
    cudaFuncSetAttribute(gemm_hmma_kernel<float>,
                         cudaFuncAttributeMaxDynamicSharedMemorySize, GEMM_SMEM);

    const int nx4 = MROWS * CDIM / 4;
    const int nw4 = CDIM * CDIM / 4;

    xconv_kernel<<<(nx4 + 255) / 256, 256>>>(x, a16, nx4);
    {
        dim3 wg((nw4 + 255) / 256, 4);
        wconv_kernel<<<wg, 256>>>(wk, wv, wr, wo, w16, nw4);
    }

    // Fused k|v|sr projection (single product), fp16 out, sigmoid cols >= 1536
    {
        dim3 fgrid(ROWS3 / 128, MROWS / 128);   // (18, 256)
        gemm_hmma_kernel<__half><<<fgrid, 256, GEMM_SMEM>>>(
            a16, w16, gkvr, ROWS3, 2 * CDIM);
    }

    // WKV scan + fused gate-mul; half2 channel-paired phases
    wkv_phase1<<<SEGTOT2 / 256, 256>>>(gkvr, sd, gagg);            // 768 CTAs
    wkv_phase2<<<LANES / 256, 256>>>(gagg, sd, gpref);
    wkv_phase3<<<SEGTOT2 / 256, 256>>>(gkvr, sd, sf, gpref, a16);  // 768 CTAs

    // Output GEMM: single product, fp32 out, N = 768
    {
        dim3 ogrid(CDIM / 128, MROWS / 128);    // (6, 256)
        gemm_hmma_kernel<float><<<ogrid, 256, GEMM_SMEM>>>(
            a16, w16 + 3 * (size_t)CDIM * CDIM, out, CDIM, 1 << 30);
    }
}